// round 1
// baseline (speedup 1.0000x reference)
#include <cuda_runtime.h>

// ---------------------------------------------------------------------------
// GatedDeltaNet  (B=2, T=4096, D=1024, H=16, DK=DV=64, KS=4)
// Round 1: correct fp32 baseline.
//   - tiled fp32 GEMMs (128x128x16, 8x8/thread)
//   - fused causal depthwise conv + SiLU + per-head L2 norm
//   - per-(b,h) sequential delta-rule recurrence, S in registers
//   - fused RMSNorm * rms_w * sigmoid-gate
// ---------------------------------------------------------------------------

#define TDIM 4096
#define BDIM 2
#define HDIM 16
#define DDIM 1024
#define MROWS (BDIM * TDIM)   // 8192

static constexpr size_t NM   = (size_t)MROWS * DDIM;          // 8388608
static constexpr size_t OF_Q  = 0;
static constexpr size_t OF_K  = 1 * NM;
static constexpr size_t OF_V  = 2 * NM;
static constexpr size_t OF_QN = 3 * NM;
static constexpr size_t OF_KN = 4 * NM;
static constexpr size_t OF_VN = 5 * NM;
static constexpr size_t OF_G  = 6 * NM;   // output gate g
static constexpr size_t OF_O  = 7 * NM;   // recurrence output
static constexpr size_t OF_OG = 8 * NM;   // gated+normed output
static constexpr size_t OF_XG = 9 * NM;                       // [8192,512]
static constexpr size_t OF_A  = OF_XG + (size_t)MROWS * 512;  // alpha [8192,16]
static constexpr size_t OF_B  = OF_A + (size_t)MROWS * HDIM;  // beta
static constexpr size_t SCRATCH_FLOATS = OF_B + (size_t)MROWS * HDIM;

__device__ float g_scratch[SCRATCH_FLOATS];

__device__ __forceinline__ float sigmoidf_(float x) {
    return 1.f / (1.f + __expf(-x));
}

// ---------------------------------------------------------------------------
// GEMM: C[M,N] = A[M,K] @ W[K,N], row-major, optional activation epilogue.
// act: 0 = none, 1 = silu, 2 = sigmoid
// A / C may live in g_scratch (pass nullptr + offset).
// ---------------------------------------------------------------------------
__global__ __launch_bounds__(256) void gemm_kernel(
    const float* __restrict__ Aext, size_t Aoff,
    const float* __restrict__ W,
    float* __restrict__ Cext, size_t Coff,
    int M, int N, int K, int act)
{
    const float* A = Aext ? Aext : (const float*)g_scratch + Aoff;
    float*       C = Cext ? Cext : g_scratch + Coff;

    __shared__ float As[16][132];   // [k][m], padded
    __shared__ float Bs[16][132];   // [k][n], padded

    const int tid  = threadIdx.x;
    const int brow = blockIdx.y * 128;
    const int bcol = blockIdx.x * 128;
    const int ty = tid >> 4;          // 0..15
    const int tx = tid & 15;          // 0..15

    // A-tile loader: float4 along k. 512 float4s, 2 per thread.
    const int a_m = tid >> 2;               // 0..63  (+64 for second)
    const int a_k = (tid & 3) << 2;         // 0,4,8,12
    // B-tile loader: float4 along n. 512 float4s, 2 per thread.
    const int b_k = tid >> 5;               // 0..7   (+8 for second)
    const int b_n = (tid & 31) << 2;        // 0..124

    float acc[8][8];
#pragma unroll
    for (int i = 0; i < 8; i++)
#pragma unroll
        for (int j = 0; j < 8; j++) acc[i][j] = 0.f;

    const float* Ap0 = A + (size_t)(brow + a_m) * K + a_k;
    const float* Ap1 = Ap0 + (size_t)64 * K;
    const float* Bp0 = W + (size_t)b_k * N + bcol + b_n;
    const float* Bp1 = Bp0 + (size_t)8 * N;

    for (int k0 = 0; k0 < K; k0 += 16) {
        float4 av0 = *(const float4*)(Ap0 + k0);
        float4 av1 = *(const float4*)(Ap1 + k0);
        float4 bv0 = *(const float4*)(Bp0 + (size_t)k0 * N);
        float4 bv1 = *(const float4*)(Bp1 + (size_t)k0 * N);

        As[a_k + 0][a_m] = av0.x;  As[a_k + 1][a_m] = av0.y;
        As[a_k + 2][a_m] = av0.z;  As[a_k + 3][a_m] = av0.w;
        As[a_k + 0][a_m + 64] = av1.x;  As[a_k + 1][a_m + 64] = av1.y;
        As[a_k + 2][a_m + 64] = av1.z;  As[a_k + 3][a_m + 64] = av1.w;
        *(float4*)&Bs[b_k][b_n]     = bv0;
        *(float4*)&Bs[b_k + 8][b_n] = bv1;
        __syncthreads();

#pragma unroll
        for (int kk = 0; kk < 16; kk++) {
            float a[8], b[8];
            *(float4*)(a)     = *(const float4*)&As[kk][ty * 8];
            *(float4*)(a + 4) = *(const float4*)&As[kk][ty * 8 + 4];
            *(float4*)(b)     = *(const float4*)&Bs[kk][tx * 8];
            *(float4*)(b + 4) = *(const float4*)&Bs[kk][tx * 8 + 4];
#pragma unroll
            for (int i = 0; i < 8; i++)
#pragma unroll
                for (int j = 0; j < 8; j++)
                    acc[i][j] = fmaf(a[i], b[j], acc[i][j]);
        }
        __syncthreads();
    }

#pragma unroll
    for (int i = 0; i < 8; i++) {
        size_t crow = (size_t)(brow + ty * 8 + i) * N + bcol + tx * 8;
#pragma unroll
        for (int jb = 0; jb < 8; jb += 4) {
            float4 v;
            float t0 = acc[i][jb + 0], t1 = acc[i][jb + 1];
            float t2 = acc[i][jb + 2], t3 = acc[i][jb + 3];
            if (act == 1) {
                t0 *= sigmoidf_(t0); t1 *= sigmoidf_(t1);
                t2 *= sigmoidf_(t2); t3 *= sigmoidf_(t3);
            } else if (act == 2) {
                t0 = sigmoidf_(t0); t1 = sigmoidf_(t1);
                t2 = sigmoidf_(t2); t3 = sigmoidf_(t3);
            }
            v.x = t0; v.y = t1; v.z = t2; v.w = t3;
            *(float4*)(C + crow + jb) = v;
        }
    }
}

// ---------------------------------------------------------------------------
// alpha/beta: per-(b,t,h) sigmoid gates. 1 warp per row; lane<16 -> alpha.
// ---------------------------------------------------------------------------
__global__ void ab_kernel(const float* __restrict__ x,
                          const float* __restrict__ Wa, const float* __restrict__ ba,
                          const float* __restrict__ Wb, const float* __restrict__ bb)
{
    int row  = blockIdx.x;
    int lane = threadIdx.x;
    const float* xr = x + (size_t)row * DDIM;
    const float* W  = (lane < 16) ? Wa : Wb;
    int h = lane & 15;

    float s0 = 0.f, s1 = 0.f, s2 = 0.f, s3 = 0.f;
#pragma unroll 4
    for (int i = 0; i < DDIM; i += 4) {
        s0 = fmaf(xr[i + 0], W[(i + 0) * HDIM + h], s0);
        s1 = fmaf(xr[i + 1], W[(i + 1) * HDIM + h], s1);
        s2 = fmaf(xr[i + 2], W[(i + 2) * HDIM + h], s2);
        s3 = fmaf(xr[i + 3], W[(i + 3) * HDIM + h], s3);
    }
    float s = (s0 + s1) + (s2 + s3);
    if (lane < 16) {
        float sg = sigmoidf_(s + ba[h]);
        g_scratch[OF_A + (size_t)row * HDIM + h] = fminf(fmaxf(sg, 0.1f), 1.0f);
    } else {
        float sg = sigmoidf_(s + bb[h]);
        g_scratch[OF_B + (size_t)row * HDIM + h] = fminf(sg, 1.0f);
    }
}

// ---------------------------------------------------------------------------
// Causal depthwise conv (K=4) + SiLU, optional per-head L2 norm.
// 1 block per (b,t) row, 1 warp per head (lane handles c, c+32).
// ---------------------------------------------------------------------------
__global__ __launch_bounds__(512) void conv_kernel(
    size_t pre_off, const float* __restrict__ w,
    const float* __restrict__ bias, size_t out_off, int do_norm)
{
    const float* pre = (const float*)g_scratch + pre_off;
    float*       out = g_scratch + out_off;

    int row  = blockIdx.x;
    int t    = row & (TDIM - 1);
    int lane = threadIdx.x & 31;
    int h    = threadIdx.x >> 5;
    int c0   = h * 64 + lane;
    int c1   = c0 + 32;

    const float* p = pre + (size_t)row * DDIM;
    float v0 = bias[c0], v1 = bias[c1];
#pragma unroll
    for (int kk = 0; kk < 4; kk++) {
        int dt = kk - 3;
        if (t + dt >= 0) {
            const float* pr = p + (ptrdiff_t)dt * DDIM;
            v0 = fmaf(w[c0 * 4 + kk], pr[c0], v0);
            v1 = fmaf(w[c1 * 4 + kk], pr[c1], v1);
        }
    }
    v0 *= sigmoidf_(v0);   // SiLU
    v1 *= sigmoidf_(v1);

    if (do_norm) {
        float ss = v0 * v0 + v1 * v1;
#pragma unroll
        for (int o = 16; o > 0; o >>= 1) ss += __shfl_xor_sync(0xffffffffu, ss, o);
        float inv = 1.f / fmaxf(sqrtf(ss), 1e-6f);
        v0 *= inv; v1 *= inv;
    }
    out[(size_t)row * DDIM + c0] = v0;
    out[(size_t)row * DDIM + c1] = v1;
}

// ---------------------------------------------------------------------------
// Gated delta-rule recurrence. 1 CTA per (b,h). 256 threads:
// thread = (column j = tid>>2, row-group ig = tid&3 -> rows ig*16..+15).
// S kept in registers; k/q/v staged through double-buffered smem (1 bar/step).
// ---------------------------------------------------------------------------
__global__ __launch_bounds__(256) void rec_kernel()
{
    const float* Q  = g_scratch + OF_QN;
    const float* Kn = g_scratch + OF_KN;
    const float* V  = g_scratch + OF_VN;
    const float* Al = g_scratch + OF_A;
    const float* Be = g_scratch + OF_B;
    float*       O  = g_scratch + OF_O;

    int bh = blockIdx.x;
    int b  = bh >> 4, h = bh & 15;
    const size_t base  = (size_t)b * TDIM * DDIM + (size_t)h * 64;
    const size_t abase = (size_t)b * TDIM * HDIM + h;

    int tid = threadIdx.x;
    int j   = tid >> 2;
    int ig  = tid & 3;
    int r0  = ig << 4;

    __shared__ float ks[2][68], qs[2][68], vs[2][64], sab[2][2];

    float S[16];
#pragma unroll
    for (int r = 0; r < 16; r++) S[r] = 0.f;

    // prologue: load t=0 into slot 0
    {
        size_t off = base;
        if (tid < 64)       { ks[0][tid + (tid >> 4)] = Kn[off + tid]; }
        else if (tid < 128) { int i = tid & 63; qs[0][i + (i >> 4)] = Q[off + i]; }
        else if (tid < 192) { int i = tid & 63; vs[0][i] = V[off + i]; }
        else if (tid == 192) sab[0][0] = Al[abase];
        else if (tid == 193) sab[0][1] = Be[abase];
    }
    __syncthreads();

    for (int t = 0; t < TDIM; t++) {
        int cur = t & 1, nxt = cur ^ 1;
        if (t + 1 < TDIM) {   // prefetch next step
            size_t off = base + (size_t)(t + 1) * DDIM;
            if (tid < 64)       { ks[nxt][tid + (tid >> 4)] = Kn[off + tid]; }
            else if (tid < 128) { int i = tid & 63; qs[nxt][i + (i >> 4)] = Q[off + i]; }
            else if (tid < 192) { int i = tid & 63; vs[nxt][i] = V[off + i]; }
            else if (tid == 192) sab[nxt][0] = Al[abase + (size_t)(t + 1) * HDIM];
            else if (tid == 193) sab[nxt][1] = Be[abase + (size_t)(t + 1) * HDIM];
        }

        float kk[16], qq[16];
#pragma unroll
        for (int r = 0; r < 16; r++) {
            int i = r0 + r;
            kk[r] = ks[cur][i + (i >> 4)];
            qq[r] = qs[cur][i + (i >> 4)];
        }
        float a = sab[cur][0], bg = sab[cur][1], vj = vs[cur][j];

        // v_hat_j partial = sum_i S[i][j] * k[i]
        float d0 = 0.f, d1 = 0.f;
#pragma unroll
        for (int r = 0; r < 16; r += 2) {
            d0 = fmaf(S[r],     kk[r],     d0);
            d1 = fmaf(S[r + 1], kk[r + 1], d1);
        }
        float dk = d0 + d1;
        dk += __shfl_xor_sync(0xffffffffu, dk, 1);
        dk += __shfl_xor_sync(0xffffffffu, dk, 2);

        float be = bg * (vj - dk);

        // S update + o_j partial = sum_i S_new[i][j] * q[i]
        float o0 = 0.f, o1 = 0.f;
#pragma unroll
        for (int r = 0; r < 16; r += 2) {
            S[r]     = fmaf(a, S[r],     be * kk[r]);
            S[r + 1] = fmaf(a, S[r + 1], be * kk[r + 1]);
            o0 = fmaf(S[r],     qq[r],     o0);
            o1 = fmaf(S[r + 1], qq[r + 1], o1);
        }
        float o = o0 + o1;
        o += __shfl_xor_sync(0xffffffffu, o, 1);
        o += __shfl_xor_sync(0xffffffffu, o, 2);
        if (ig == 0) O[base + (size_t)t * DDIM + j] = o;

        __syncthreads();
    }
}

// ---------------------------------------------------------------------------
// RMSNorm (per head, DV=64) * rms_w * output gate g  -> Og
// ---------------------------------------------------------------------------
__global__ __launch_bounds__(512) void post_kernel(const float* __restrict__ rms_w)
{
    const float* O  = g_scratch + OF_O;
    const float* G  = g_scratch + OF_G;
    float*       Og = g_scratch + OF_OG;

    int row  = blockIdx.x;
    int lane = threadIdx.x & 31;
    int h    = threadIdx.x >> 5;
    size_t i0 = (size_t)row * DDIM + h * 64 + lane;

    float v0 = O[i0], v1 = O[i0 + 32];
    float ss = v0 * v0 + v1 * v1;
#pragma unroll
    for (int o = 16; o > 0; o >>= 1) ss += __shfl_xor_sync(0xffffffffu, ss, o);
    float inv = rsqrtf(ss * (1.f / 64.f) + 1e-6f);

    v0 = v0 * inv * rms_w[h * 64 + lane]      * G[i0];
    v1 = v1 * inv * rms_w[h * 64 + lane + 32] * G[i0 + 32];
    Og[i0]      = v0;
    Og[i0 + 32] = v1;
}

// ---------------------------------------------------------------------------
extern "C" void kernel_launch(void* const* d_in, const int* in_sizes, int n_in,
                              void* d_out, int out_size)
{
    (void)in_sizes; (void)n_in; (void)out_size;
    const float* x   = (const float*)d_in[0];
    const float* Wq  = (const float*)d_in[1];
    const float* Wk  = (const float*)d_in[2];
    const float* Wv  = (const float*)d_in[3];
    const float* Wo  = (const float*)d_in[4];
    const float* Wa  = (const float*)d_in[5];
    const float* ba  = (const float*)d_in[6];
    const float* Wb  = (const float*)d_in[7];
    const float* bb  = (const float*)d_in[8];
    const float* Wgd = (const float*)d_in[9];
    const float* Wgu = (const float*)d_in[10];
    const float* rms = (const float*)d_in[11];
    const float* qcw = (const float*)d_in[12];
    const float* qcb = (const float*)d_in[13];
    const float* kcw = (const float*)d_in[14];
    const float* kcb = (const float*)d_in[15];
    const float* vcw = (const float*)d_in[16];
    const float* vcb = (const float*)d_in[17];
    float* out = (float*)d_out;

    dim3 g1024(1024 / 128, MROWS / 128);   // (8, 64)
    dim3 g512 (512 / 128,  MROWS / 128);   // (4, 64)

    // projections
    gemm_kernel<<<g1024, 256>>>(x, 0, Wq, nullptr, OF_Q, MROWS, 1024, 1024, 0);
    gemm_kernel<<<g1024, 256>>>(x, 0, Wk, nullptr, OF_K, MROWS, 1024, 1024, 0);
    gemm_kernel<<<g1024, 256>>>(x, 0, Wv, nullptr, OF_V, MROWS, 1024, 1024, 0);
    // output-gate MLP: silu(x@Wgd) @ Wgu -> sigmoid
    gemm_kernel<<<g512,  256>>>(x, 0, Wgd, nullptr, OF_XG, MROWS, 512, 1024, 1);
    gemm_kernel<<<g1024, 256>>>(nullptr, OF_XG, Wgu, nullptr, OF_G, MROWS, 1024, 512, 2);
    // per-head scalar gates
    ab_kernel<<<MROWS, 32>>>(x, Wa, ba, Wb, bb);
    // causal conv + SiLU (+ L2 norm for q,k)
    conv_kernel<<<MROWS, 512>>>(OF_Q, qcw, qcb, OF_QN, 1);
    conv_kernel<<<MROWS, 512>>>(OF_K, kcw, kcb, OF_KN, 1);
    conv_kernel<<<MROWS, 512>>>(OF_V, vcw, vcb, OF_VN, 0);
    // sequential delta-rule recurrence
    rec_kernel<<<BDIM * HDIM, 256>>>();
    // RMSNorm + gate
    post_kernel<<<MROWS, 512>>>(rms);
    // final projection
    gemm_kernel<<<g1024, 256>>>(nullptr, OF_OG, Wo, out, 0, MROWS, 1024, 1024, 0);
}

// round 2
// speedup vs baseline: 1.6880x; 1.6880x over previous
#include <cuda_runtime.h>

// ---------------------------------------------------------------------------
// GatedDeltaNet  (B=2, T=4096, D=1024, H=16, DK=DV=64, KS=4)
// Round 2:
//   - GEMMs: double-buffered smem, 1 sync/tile, register prefetch
//   - recurrence: 8-timestep staged double buffer (1 sync / 8 steps)
//   - ab_kernel occupancy fix
// ---------------------------------------------------------------------------

#define TDIM 4096
#define BDIM 2
#define HDIM 16
#define DDIM 1024
#define MROWS (BDIM * TDIM)   // 8192
#define STAGE 8

static constexpr size_t NM   = (size_t)MROWS * DDIM;          // 8388608
static constexpr size_t OF_Q  = 0;
static constexpr size_t OF_K  = 1 * NM;
static constexpr size_t OF_V  = 2 * NM;
static constexpr size_t OF_QN = 3 * NM;
static constexpr size_t OF_KN = 4 * NM;
static constexpr size_t OF_VN = 5 * NM;
static constexpr size_t OF_G  = 6 * NM;   // output gate g
static constexpr size_t OF_O  = 7 * NM;   // recurrence output
static constexpr size_t OF_OG = 8 * NM;   // gated+normed output
static constexpr size_t OF_XG = 9 * NM;                       // [8192,512]
static constexpr size_t OF_A  = OF_XG + (size_t)MROWS * 512;  // alpha [8192,16]
static constexpr size_t OF_B  = OF_A + (size_t)MROWS * HDIM;  // beta
static constexpr size_t SCRATCH_FLOATS = OF_B + (size_t)MROWS * HDIM;

__device__ float g_scratch[SCRATCH_FLOATS];

__device__ __forceinline__ float sigmoidf_(float x) {
    return 1.f / (1.f + __expf(-x));
}

// ---------------------------------------------------------------------------
// GEMM: C[M,N] = A[M,K] @ W[K,N], row-major, optional activation epilogue.
// act: 0 = none, 1 = silu, 2 = sigmoid
// Double-buffered smem: one __syncthreads per 16-wide k-tile.
// ---------------------------------------------------------------------------
__global__ __launch_bounds__(256) void gemm_kernel(
    const float* __restrict__ Aext, size_t Aoff,
    const float* __restrict__ W,
    float* __restrict__ Cext, size_t Coff,
    int M, int N, int K, int act)
{
    const float* A = Aext ? Aext : (const float*)g_scratch + Aoff;
    float*       C = Cext ? Cext : g_scratch + Coff;

    __shared__ float As[2][16][132];   // [buf][k][m], padded
    __shared__ float Bs[2][16][132];   // [buf][k][n], padded

    const int tid  = threadIdx.x;
    const int brow = blockIdx.y * 128;
    const int bcol = blockIdx.x * 128;
    const int ty = tid >> 4;          // 0..15
    const int tx = tid & 15;          // 0..15

    const int a_m = tid >> 2;               // 0..63  (+64 for second)
    const int a_k = (tid & 3) << 2;         // 0,4,8,12
    const int b_k = tid >> 5;               // 0..7   (+8 for second)
    const int b_n = (tid & 31) << 2;        // 0..124

    const float* Ap0 = A + (size_t)(brow + a_m) * K + a_k;
    const float* Ap1 = Ap0 + (size_t)64 * K;
    const float* Bp0 = W + (size_t)b_k * N + bcol + b_n;
    const float* Bp1 = Bp0 + (size_t)8 * N;

    float acc[8][8];
#pragma unroll
    for (int i = 0; i < 8; i++)
#pragma unroll
        for (int j = 0; j < 8; j++) acc[i][j] = 0.f;

    // prologue: tile 0 -> smem buf 0
    {
        float4 av0 = *(const float4*)(Ap0);
        float4 av1 = *(const float4*)(Ap1);
        float4 bv0 = *(const float4*)(Bp0);
        float4 bv1 = *(const float4*)(Bp1);
        As[0][a_k + 0][a_m] = av0.x;  As[0][a_k + 1][a_m] = av0.y;
        As[0][a_k + 2][a_m] = av0.z;  As[0][a_k + 3][a_m] = av0.w;
        As[0][a_k + 0][a_m + 64] = av1.x;  As[0][a_k + 1][a_m + 64] = av1.y;
        As[0][a_k + 2][a_m + 64] = av1.z;  As[0][a_k + 3][a_m + 64] = av1.w;
        *(float4*)&Bs[0][b_k][b_n]     = bv0;
        *(float4*)&Bs[0][b_k + 8][b_n] = bv1;
    }
    __syncthreads();

    const int nk = K >> 4;
    float4 pav0, pav1, pbv0, pbv1;
    if (nk > 1) {
        pav0 = *(const float4*)(Ap0 + 16);
        pav1 = *(const float4*)(Ap1 + 16);
        pbv0 = *(const float4*)(Bp0 + (size_t)16 * N);
        pbv1 = *(const float4*)(Bp1 + (size_t)16 * N);
    }

    for (int kt = 0; kt < nk; kt++) {
        const int cur = kt & 1;
#pragma unroll
        for (int kk = 0; kk < 16; kk++) {
            float a[8], b[8];
            *(float4*)(a)     = *(const float4*)&As[cur][kk][ty * 8];
            *(float4*)(a + 4) = *(const float4*)&As[cur][kk][ty * 8 + 4];
            *(float4*)(b)     = *(const float4*)&Bs[cur][kk][tx * 8];
            *(float4*)(b + 4) = *(const float4*)&Bs[cur][kk][tx * 8 + 4];
#pragma unroll
            for (int i = 0; i < 8; i++)
#pragma unroll
                for (int j = 0; j < 8; j++)
                    acc[i][j] = fmaf(a[i], b[j], acc[i][j]);
        }
        if (kt + 1 < nk) {
            const int nxt = cur ^ 1;
            As[nxt][a_k + 0][a_m] = pav0.x;  As[nxt][a_k + 1][a_m] = pav0.y;
            As[nxt][a_k + 2][a_m] = pav0.z;  As[nxt][a_k + 3][a_m] = pav0.w;
            As[nxt][a_k + 0][a_m + 64] = pav1.x;  As[nxt][a_k + 1][a_m + 64] = pav1.y;
            As[nxt][a_k + 2][a_m + 64] = pav1.z;  As[nxt][a_k + 3][a_m + 64] = pav1.w;
            *(float4*)&Bs[nxt][b_k][b_n]     = pbv0;
            *(float4*)&Bs[nxt][b_k + 8][b_n] = pbv1;
            __syncthreads();
            if (kt + 2 < nk) {
                const int ko = (kt + 2) << 4;
                pav0 = *(const float4*)(Ap0 + ko);
                pav1 = *(const float4*)(Ap1 + ko);
                pbv0 = *(const float4*)(Bp0 + (size_t)ko * N);
                pbv1 = *(const float4*)(Bp1 + (size_t)ko * N);
            }
        }
    }

#pragma unroll
    for (int i = 0; i < 8; i++) {
        size_t crow = (size_t)(brow + ty * 8 + i) * N + bcol + tx * 8;
#pragma unroll
        for (int jb = 0; jb < 8; jb += 4) {
            float4 v;
            float t0 = acc[i][jb + 0], t1 = acc[i][jb + 1];
            float t2 = acc[i][jb + 2], t3 = acc[i][jb + 3];
            if (act == 1) {
                t0 *= sigmoidf_(t0); t1 *= sigmoidf_(t1);
                t2 *= sigmoidf_(t2); t3 *= sigmoidf_(t3);
            } else if (act == 2) {
                t0 = sigmoidf_(t0); t1 = sigmoidf_(t1);
                t2 = sigmoidf_(t2); t3 = sigmoidf_(t3);
            }
            v.x = t0; v.y = t1; v.z = t2; v.w = t3;
            *(float4*)(C + crow + jb) = v;
        }
    }
}

// ---------------------------------------------------------------------------
// alpha/beta gates: 8 warps per block, 1 warp per row; lane<16 -> alpha.
// ---------------------------------------------------------------------------
__global__ __launch_bounds__(256) void ab_kernel(
    const float* __restrict__ x,
    const float* __restrict__ Wa, const float* __restrict__ ba,
    const float* __restrict__ Wb, const float* __restrict__ bb)
{
    int row  = blockIdx.x * 8 + (threadIdx.x >> 5);
    int lane = threadIdx.x & 31;
    const float* xr = x + (size_t)row * DDIM;
    const float* W  = (lane < 16) ? Wa : Wb;
    int h = lane & 15;

    float s0 = 0.f, s1 = 0.f, s2 = 0.f, s3 = 0.f;
#pragma unroll 4
    for (int i = 0; i < DDIM; i += 4) {
        s0 = fmaf(xr[i + 0], W[(i + 0) * HDIM + h], s0);
        s1 = fmaf(xr[i + 1], W[(i + 1) * HDIM + h], s1);
        s2 = fmaf(xr[i + 2], W[(i + 2) * HDIM + h], s2);
        s3 = fmaf(xr[i + 3], W[(i + 3) * HDIM + h], s3);
    }
    float s = (s0 + s1) + (s2 + s3);
    if (lane < 16) {
        float sg = sigmoidf_(s + ba[h]);
        g_scratch[OF_A + (size_t)row * HDIM + h] = fminf(fmaxf(sg, 0.1f), 1.0f);
    } else {
        float sg = sigmoidf_(s + bb[h]);
        g_scratch[OF_B + (size_t)row * HDIM + h] = fminf(sg, 1.0f);
    }
}

// ---------------------------------------------------------------------------
// Causal depthwise conv (K=4) + SiLU, optional per-head L2 norm.
// ---------------------------------------------------------------------------
__global__ __launch_bounds__(512) void conv_kernel(
    size_t pre_off, const float* __restrict__ w,
    const float* __restrict__ bias, size_t out_off, int do_norm)
{
    const float* pre = (const float*)g_scratch + pre_off;
    float*       out = g_scratch + out_off;

    int row  = blockIdx.x;
    int t    = row & (TDIM - 1);
    int lane = threadIdx.x & 31;
    int h    = threadIdx.x >> 5;
    int c0   = h * 64 + lane;
    int c1   = c0 + 32;

    const float* p = pre + (size_t)row * DDIM;
    float v0 = bias[c0], v1 = bias[c1];
#pragma unroll
    for (int kk = 0; kk < 4; kk++) {
        int dt = kk - 3;
        if (t + dt >= 0) {
            const float* pr = p + (ptrdiff_t)dt * DDIM;
            v0 = fmaf(w[c0 * 4 + kk], pr[c0], v0);
            v1 = fmaf(w[c1 * 4 + kk], pr[c1], v1);
        }
    }
    v0 *= sigmoidf_(v0);   // SiLU
    v1 *= sigmoidf_(v1);

    if (do_norm) {
        float ss = v0 * v0 + v1 * v1;
#pragma unroll
        for (int o = 16; o > 0; o >>= 1) ss += __shfl_xor_sync(0xffffffffu, ss, o);
        float inv = 1.f / fmaxf(sqrtf(ss), 1e-6f);
        v0 *= inv; v1 *= inv;
    }
    out[(size_t)row * DDIM + c0] = v0;
    out[(size_t)row * DDIM + c1] = v1;
}

// ---------------------------------------------------------------------------
// Staged loader for the recurrence: one stage = STAGE timesteps of k/q/v/a/b.
// 384 float4 vector loads + 16 scalar loads, spread over 256 threads.
// ---------------------------------------------------------------------------
__device__ __forceinline__ void rec_load(
    float* sk, float* sq, float* sv, float* sa, float* sb,
    const float* __restrict__ Kn, const float* __restrict__ Q,
    const float* __restrict__ V,
    const float* __restrict__ Al, const float* __restrict__ Be,
    size_t base, size_t abase, int t0, int tid)
{
#pragma unroll
    for (int l = 0; l < 2; l++) {
        int idx = tid + 256 * l;
        if (idx < 384) {
            int arr = idx >> 7;            // 0=k, 1=q, 2=v
            int rem = idx & 127;
            int e   = rem >> 4;
            int vec = (rem & 15) << 2;
            const float* src = (arr == 0) ? Kn : (arr == 1) ? Q : V;
            float*       dst = (arr == 0) ? sk : (arr == 1) ? sq : sv;
            float4 val = *(const float4*)(src + base + (size_t)(t0 + e) * DDIM + vec);
            *(float4*)(dst + e * 64 + vec) = val;
        } else if (idx < 384 + STAGE) {
            int e = idx - 384;
            sa[e] = Al[abase + (size_t)(t0 + e) * HDIM];
        } else if (idx < 384 + 2 * STAGE) {
            int e = idx - 384 - STAGE;
            sb[e] = Be[abase + (size_t)(t0 + e) * HDIM];
        }
    }
}

// ---------------------------------------------------------------------------
// Gated delta-rule recurrence. 1 CTA per (b,h). 256 threads:
// thread = (column j = tid>>2, row-group ig = tid&3 -> rows ig*16..+15).
// S in registers; inputs staged 8 timesteps at a time, double-buffered.
// ---------------------------------------------------------------------------
__global__ __launch_bounds__(256) void rec_kernel()
{
    const float* Q  = g_scratch + OF_QN;
    const float* Kn = g_scratch + OF_KN;
    const float* V  = g_scratch + OF_VN;
    const float* Al = g_scratch + OF_A;
    const float* Be = g_scratch + OF_B;
    float*       O  = g_scratch + OF_O;

    int bh = blockIdx.x;
    int b  = bh >> 4, h = bh & 15;
    const size_t base  = (size_t)b * TDIM * DDIM + (size_t)h * 64;
    const size_t abase = (size_t)b * TDIM * HDIM + h;

    int tid = threadIdx.x;
    int j   = tid >> 2;
    int ig  = tid & 3;
    int r0  = ig << 4;

    __shared__ float sk[2][STAGE * 64];
    __shared__ float sq[2][STAGE * 64];
    __shared__ float sv[2][STAGE * 64];
    __shared__ float sa[2][STAGE];
    __shared__ float sb[2][STAGE];

    float S[16];
#pragma unroll
    for (int r = 0; r < 16; r++) S[r] = 0.f;

    rec_load(sk[0], sq[0], sv[0], sa[0], sb[0], Kn, Q, V, Al, Be,
             base, abase, 0, tid);
    __syncthreads();

    const int nstages = TDIM / STAGE;   // 512
    for (int s = 0; s < nstages; s++) {
        const int buf = s & 1;
        if (s + 1 < nstages) {
            rec_load(sk[buf ^ 1], sq[buf ^ 1], sv[buf ^ 1], sa[buf ^ 1], sb[buf ^ 1],
                     Kn, Q, V, Al, Be, base, abase, (s + 1) * STAGE, tid);
        }

        const float* kbuf = sk[buf];
        const float* qbuf = sq[buf];
        const float* vbuf = sv[buf];

#pragma unroll
        for (int e = 0; e < STAGE; e++) {
            float kk[16], qq[16];
#pragma unroll
            for (int c = 0; c < 4; c++) {
                *(float4*)(kk + c * 4) = *(const float4*)(kbuf + e * 64 + r0 + c * 4);
                *(float4*)(qq + c * 4) = *(const float4*)(qbuf + e * 64 + r0 + c * 4);
            }
            float a  = sa[buf][e];
            float bg = sb[buf][e];
            float vj = vbuf[e * 64 + j];

            // v_hat_j partial = sum_i S[i][j] * k[i]
            float d0 = 0.f, d1 = 0.f;
#pragma unroll
            for (int r = 0; r < 16; r += 2) {
                d0 = fmaf(S[r],     kk[r],     d0);
                d1 = fmaf(S[r + 1], kk[r + 1], d1);
            }
            float dk = d0 + d1;
            dk += __shfl_xor_sync(0xffffffffu, dk, 1);
            dk += __shfl_xor_sync(0xffffffffu, dk, 2);

            float be = bg * (vj - dk);

            // S update + o_j partial = sum_i S_new[i][j] * q[i]
            float o0 = 0.f, o1 = 0.f;
#pragma unroll
            for (int r = 0; r < 16; r += 2) {
                S[r]     = fmaf(a, S[r],     be * kk[r]);
                S[r + 1] = fmaf(a, S[r + 1], be * kk[r + 1]);
                o0 = fmaf(S[r],     qq[r],     o0);
                o1 = fmaf(S[r + 1], qq[r + 1], o1);
            }
            float o = o0 + o1;
            o += __shfl_xor_sync(0xffffffffu, o, 1);
            o += __shfl_xor_sync(0xffffffffu, o, 2);
            if (ig == 0) O[base + (size_t)(s * STAGE + e) * DDIM + j] = o;
        }
        __syncthreads();
    }
}

// ---------------------------------------------------------------------------
// RMSNorm (per head, DV=64) * rms_w * output gate g  -> Og
// ---------------------------------------------------------------------------
__global__ __launch_bounds__(512) void post_kernel(const float* __restrict__ rms_w)
{
    const float* O  = g_scratch + OF_O;
    const float* G  = g_scratch + OF_G;
    float*       Og = g_scratch + OF_OG;

    int row  = blockIdx.x;
    int lane = threadIdx.x & 31;
    int h    = threadIdx.x >> 5;
    size_t i0 = (size_t)row * DDIM + h * 64 + lane;

    float v0 = O[i0], v1 = O[i0 + 32];
    float ss = v0 * v0 + v1 * v1;
#pragma unroll
    for (int o = 16; o > 0; o >>= 1) ss += __shfl_xor_sync(0xffffffffu, ss, o);
    float inv = rsqrtf(ss * (1.f / 64.f) + 1e-6f);

    v0 = v0 * inv * rms_w[h * 64 + lane]      * G[i0];
    v1 = v1 * inv * rms_w[h * 64 + lane + 32] * G[i0 + 32];
    Og[i0]      = v0;
    Og[i0 + 32] = v1;
}

// ---------------------------------------------------------------------------
extern "C" void kernel_launch(void* const* d_in, const int* in_sizes, int n_in,
                              void* d_out, int out_size)
{
    (void)in_sizes; (void)n_in; (void)out_size;
    const float* x   = (const float*)d_in[0];
    const float* Wq  = (const float*)d_in[1];
    const float* Wk  = (const float*)d_in[2];
    const float* Wv  = (const float*)d_in[3];
    const float* Wo  = (const float*)d_in[4];
    const float* Wa  = (const float*)d_in[5];
    const float* ba  = (const float*)d_in[6];
    const float* Wb  = (const float*)d_in[7];
    const float* bb  = (const float*)d_in[8];
    const float* Wgd = (const float*)d_in[9];
    const float* Wgu = (const float*)d_in[10];
    const float* rms = (const float*)d_in[11];
    const float* qcw = (const float*)d_in[12];
    const float* qcb = (const float*)d_in[13];
    const float* kcw = (const float*)d_in[14];
    const float* kcb = (const float*)d_in[15];
    const float* vcw = (const float*)d_in[16];
    const float* vcb = (const float*)d_in[17];
    float* out = (float*)d_out;

    dim3 g1024(1024 / 128, MROWS / 128);   // (8, 64)
    dim3 g512 (512 / 128,  MROWS / 128);   // (4, 64)

    // projections
    gemm_kernel<<<g1024, 256>>>(x, 0, Wq, nullptr, OF_Q, MROWS, 1024, 1024, 0);
    gemm_kernel<<<g1024, 256>>>(x, 0, Wk, nullptr, OF_K, MROWS, 1024, 1024, 0);
    gemm_kernel<<<g1024, 256>>>(x, 0, Wv, nullptr, OF_V, MROWS, 1024, 1024, 0);
    // output-gate MLP: silu(x@Wgd) @ Wgu -> sigmoid
    gemm_kernel<<<g512,  256>>>(x, 0, Wgd, nullptr, OF_XG, MROWS, 512, 1024, 1);
    gemm_kernel<<<g1024, 256>>>(nullptr, OF_XG, Wgu, nullptr, OF_G, MROWS, 1024, 512, 2);
    // per-head scalar gates
    ab_kernel<<<MROWS / 8, 256>>>(x, Wa, ba, Wb, bb);
    // causal conv + SiLU (+ L2 norm for q,k)
    conv_kernel<<<MROWS, 512>>>(OF_Q, qcw, qcb, OF_QN, 1);
    conv_kernel<<<MROWS, 512>>>(OF_K, kcw, kcb, OF_KN, 1);
    conv_kernel<<<MROWS, 512>>>(OF_V, vcw, vcb, OF_VN, 0);
    // sequential delta-rule recurrence
    rec_kernel<<<BDIM * HDIM, 256>>>();
    // RMSNorm + gate
    post_kernel<<<MROWS, 512>>>(rms);
    // final projection
    gemm_kernel<<<g1024, 256>>>(nullptr, OF_OG, Wo, out, 0, MROWS, 1024, 1024, 0);
}

// round 3
// speedup vs baseline: 1.8813x; 1.1145x over previous
#include <cuda_runtime.h>

// ---------------------------------------------------------------------------
// GatedDeltaNet  (B=2, T=4096, D=1024, H=16, DK=DV=64, KS=4)
// Round 3:
//   - recurrence: column-split 4 CTAs/(b,h) (128 CTAs), f32x2 packed math,
//     fused u/w/kq single shfl chain, o = a*w + be*err*kq refactor
//   - conv q/k/v fused into one launch (grid.y)
//   - GEMMs unchanged (smem-BW/FMA co-bound; tensor cores next round)
// ---------------------------------------------------------------------------

#define TDIM 4096
#define BDIM 2
#define HDIM 16
#define DDIM 1024
#define MROWS (BDIM * TDIM)   // 8192
#define STAGE 8

typedef unsigned long long ull;

static constexpr size_t NM   = (size_t)MROWS * DDIM;          // 8388608
static constexpr size_t OF_Q  = 0;
static constexpr size_t OF_K  = 1 * NM;
static constexpr size_t OF_V  = 2 * NM;
static constexpr size_t OF_QN = 3 * NM;
static constexpr size_t OF_KN = 4 * NM;
static constexpr size_t OF_VN = 5 * NM;
static constexpr size_t OF_G  = 6 * NM;   // output gate g
static constexpr size_t OF_O  = 7 * NM;   // recurrence output
static constexpr size_t OF_OG = 8 * NM;   // gated+normed output
static constexpr size_t OF_XG = 9 * NM;                       // [8192,512]
static constexpr size_t OF_A  = OF_XG + (size_t)MROWS * 512;  // alpha [8192,16]
static constexpr size_t OF_B  = OF_A + (size_t)MROWS * HDIM;  // beta
static constexpr size_t SCRATCH_FLOATS = OF_B + (size_t)MROWS * HDIM;

__device__ float g_scratch[SCRATCH_FLOATS];

__device__ __forceinline__ float sigmoidf_(float x) {
    return 1.f / (1.f + __expf(-x));
}

// ---- f32x2 packed helpers (sm_103a) ---------------------------------------
__device__ __forceinline__ ull fma2_(ull a, ull b, ull c) {
    ull d;
    asm("fma.rn.f32x2 %0, %1, %2, %3;" : "=l"(d) : "l"(a), "l"(b), "l"(c));
    return d;
}
__device__ __forceinline__ ull mul2_(ull a, ull b) {
    ull d;
    asm("mul.rn.f32x2 %0, %1, %2;" : "=l"(d) : "l"(a), "l"(b));
    return d;
}
__device__ __forceinline__ ull pack2_(float x) {
    ull r;
    asm("mov.b64 %0, {%1, %1};" : "=l"(r) : "r"(__float_as_uint(x)));
    return r;
}
__device__ __forceinline__ float hadd2_(ull a) {
    unsigned lo, hi;
    asm("mov.b64 {%0, %1}, %2;" : "=r"(lo), "=r"(hi) : "l"(a));
    return __uint_as_float(lo) + __uint_as_float(hi);
}

// ---------------------------------------------------------------------------
// GEMM: C[M,N] = A[M,K] @ W[K,N], row-major, optional activation epilogue.
// act: 0 = none, 1 = silu, 2 = sigmoid.  Double-buffered smem.
// ---------------------------------------------------------------------------
__global__ __launch_bounds__(256) void gemm_kernel(
    const float* __restrict__ Aext, size_t Aoff,
    const float* __restrict__ W,
    float* __restrict__ Cext, size_t Coff,
    int M, int N, int K, int act)
{
    const float* A = Aext ? Aext : (const float*)g_scratch + Aoff;
    float*       C = Cext ? Cext : g_scratch + Coff;

    __shared__ float As[2][16][132];
    __shared__ float Bs[2][16][132];

    const int tid  = threadIdx.x;
    const int brow = blockIdx.y * 128;
    const int bcol = blockIdx.x * 128;
    const int ty = tid >> 4;
    const int tx = tid & 15;

    const int a_m = tid >> 2;
    const int a_k = (tid & 3) << 2;
    const int b_k = tid >> 5;
    const int b_n = (tid & 31) << 2;

    const float* Ap0 = A + (size_t)(brow + a_m) * K + a_k;
    const float* Ap1 = Ap0 + (size_t)64 * K;
    const float* Bp0 = W + (size_t)b_k * N + bcol + b_n;
    const float* Bp1 = Bp0 + (size_t)8 * N;

    float acc[8][8];
#pragma unroll
    for (int i = 0; i < 8; i++)
#pragma unroll
        for (int j = 0; j < 8; j++) acc[i][j] = 0.f;

    {
        float4 av0 = *(const float4*)(Ap0);
        float4 av1 = *(const float4*)(Ap1);
        float4 bv0 = *(const float4*)(Bp0);
        float4 bv1 = *(const float4*)(Bp1);
        As[0][a_k + 0][a_m] = av0.x;  As[0][a_k + 1][a_m] = av0.y;
        As[0][a_k + 2][a_m] = av0.z;  As[0][a_k + 3][a_m] = av0.w;
        As[0][a_k + 0][a_m + 64] = av1.x;  As[0][a_k + 1][a_m + 64] = av1.y;
        As[0][a_k + 2][a_m + 64] = av1.z;  As[0][a_k + 3][a_m + 64] = av1.w;
        *(float4*)&Bs[0][b_k][b_n]     = bv0;
        *(float4*)&Bs[0][b_k + 8][b_n] = bv1;
    }
    __syncthreads();

    const int nk = K >> 4;
    float4 pav0, pav1, pbv0, pbv1;
    if (nk > 1) {
        pav0 = *(const float4*)(Ap0 + 16);
        pav1 = *(const float4*)(Ap1 + 16);
        pbv0 = *(const float4*)(Bp0 + (size_t)16 * N);
        pbv1 = *(const float4*)(Bp1 + (size_t)16 * N);
    }

    for (int kt = 0; kt < nk; kt++) {
        const int cur = kt & 1;
#pragma unroll
        for (int kk = 0; kk < 16; kk++) {
            float a[8], b[8];
            *(float4*)(a)     = *(const float4*)&As[cur][kk][ty * 8];
            *(float4*)(a + 4) = *(const float4*)&As[cur][kk][ty * 8 + 4];
            *(float4*)(b)     = *(const float4*)&Bs[cur][kk][tx * 8];
            *(float4*)(b + 4) = *(const float4*)&Bs[cur][kk][tx * 8 + 4];
#pragma unroll
            for (int i = 0; i < 8; i++)
#pragma unroll
                for (int j = 0; j < 8; j++)
                    acc[i][j] = fmaf(a[i], b[j], acc[i][j]);
        }
        if (kt + 1 < nk) {
            const int nxt = cur ^ 1;
            As[nxt][a_k + 0][a_m] = pav0.x;  As[nxt][a_k + 1][a_m] = pav0.y;
            As[nxt][a_k + 2][a_m] = pav0.z;  As[nxt][a_k + 3][a_m] = pav0.w;
            As[nxt][a_k + 0][a_m + 64] = pav1.x;  As[nxt][a_k + 1][a_m + 64] = pav1.y;
            As[nxt][a_k + 2][a_m + 64] = pav1.z;  As[nxt][a_k + 3][a_m + 64] = pav1.w;
            *(float4*)&Bs[nxt][b_k][b_n]     = pbv0;
            *(float4*)&Bs[nxt][b_k + 8][b_n] = pbv1;
            __syncthreads();
            if (kt + 2 < nk) {
                const int ko = (kt + 2) << 4;
                pav0 = *(const float4*)(Ap0 + ko);
                pav1 = *(const float4*)(Ap1 + ko);
                pbv0 = *(const float4*)(Bp0 + (size_t)ko * N);
                pbv1 = *(const float4*)(Bp1 + (size_t)ko * N);
            }
        }
    }

#pragma unroll
    for (int i = 0; i < 8; i++) {
        size_t crow = (size_t)(brow + ty * 8 + i) * N + bcol + tx * 8;
#pragma unroll
        for (int jb = 0; jb < 8; jb += 4) {
            float4 v;
            float t0 = acc[i][jb + 0], t1 = acc[i][jb + 1];
            float t2 = acc[i][jb + 2], t3 = acc[i][jb + 3];
            if (act == 1) {
                t0 *= sigmoidf_(t0); t1 *= sigmoidf_(t1);
                t2 *= sigmoidf_(t2); t3 *= sigmoidf_(t3);
            } else if (act == 2) {
                t0 = sigmoidf_(t0); t1 = sigmoidf_(t1);
                t2 = sigmoidf_(t2); t3 = sigmoidf_(t3);
            }
            v.x = t0; v.y = t1; v.z = t2; v.w = t3;
            *(float4*)(C + crow + jb) = v;
        }
    }
}

// ---------------------------------------------------------------------------
// alpha/beta gates: 8 warps per block, 1 warp per row; lane<16 -> alpha.
// ---------------------------------------------------------------------------
__global__ __launch_bounds__(256) void ab_kernel(
    const float* __restrict__ x,
    const float* __restrict__ Wa, const float* __restrict__ ba,
    const float* __restrict__ Wb, const float* __restrict__ bb)
{
    int row  = blockIdx.x * 8 + (threadIdx.x >> 5);
    int lane = threadIdx.x & 31;
    const float* xr = x + (size_t)row * DDIM;
    const float* W  = (lane < 16) ? Wa : Wb;
    int h = lane & 15;

    float s0 = 0.f, s1 = 0.f, s2 = 0.f, s3 = 0.f;
#pragma unroll 4
    for (int i = 0; i < DDIM; i += 4) {
        s0 = fmaf(xr[i + 0], W[(i + 0) * HDIM + h], s0);
        s1 = fmaf(xr[i + 1], W[(i + 1) * HDIM + h], s1);
        s2 = fmaf(xr[i + 2], W[(i + 2) * HDIM + h], s2);
        s3 = fmaf(xr[i + 3], W[(i + 3) * HDIM + h], s3);
    }
    float s = (s0 + s1) + (s2 + s3);
    if (lane < 16) {
        float sg = sigmoidf_(s + ba[h]);
        g_scratch[OF_A + (size_t)row * HDIM + h] = fminf(fmaxf(sg, 0.1f), 1.0f);
    } else {
        float sg = sigmoidf_(s + bb[h]);
        g_scratch[OF_B + (size_t)row * HDIM + h] = fminf(sg, 1.0f);
    }
}

// ---------------------------------------------------------------------------
// Causal depthwise conv (K=4) + SiLU (+ L2 norm for q,k).
// One fused launch: blockIdx.y = 0(q) / 1(k) / 2(v).
// ---------------------------------------------------------------------------
__global__ __launch_bounds__(512) void conv_kernel(
    const float* __restrict__ qcw, const float* __restrict__ qcb,
    const float* __restrict__ kcw, const float* __restrict__ kcb,
    const float* __restrict__ vcw, const float* __restrict__ vcb)
{
    int which = blockIdx.y;
    const float* w;
    const float* bias;
    size_t pre_off, out_off;
    int do_norm;
    if (which == 0) { w = qcw; bias = qcb; pre_off = OF_Q; out_off = OF_QN; do_norm = 1; }
    else if (which == 1) { w = kcw; bias = kcb; pre_off = OF_K; out_off = OF_KN; do_norm = 1; }
    else { w = vcw; bias = vcb; pre_off = OF_V; out_off = OF_VN; do_norm = 0; }

    const float* pre = (const float*)g_scratch + pre_off;
    float*       out = g_scratch + out_off;

    int row  = blockIdx.x;
    int t    = row & (TDIM - 1);
    int lane = threadIdx.x & 31;
    int h    = threadIdx.x >> 5;
    int c0   = h * 64 + lane;
    int c1   = c0 + 32;

    const float* p = pre + (size_t)row * DDIM;
    float v0 = bias[c0], v1 = bias[c1];
#pragma unroll
    for (int kk = 0; kk < 4; kk++) {
        int dt = kk - 3;
        if (t + dt >= 0) {
            const float* pr = p + (ptrdiff_t)dt * DDIM;
            v0 = fmaf(w[c0 * 4 + kk], pr[c0], v0);
            v1 = fmaf(w[c1 * 4 + kk], pr[c1], v1);
        }
    }
    v0 *= sigmoidf_(v0);   // SiLU
    v1 *= sigmoidf_(v1);

    if (do_norm) {
        float ss = v0 * v0 + v1 * v1;
#pragma unroll
        for (int o = 16; o > 0; o >>= 1) ss += __shfl_xor_sync(0xffffffffu, ss, o);
        float inv = 1.f / fmaxf(sqrtf(ss), 1e-6f);
        v0 *= inv; v1 *= inv;
    }
    out[(size_t)row * DDIM + c0] = v0;
    out[(size_t)row * DDIM + c1] = v1;
}

// ---------------------------------------------------------------------------
// Recurrence stage loader: STAGE=8 timesteps of k(64), q(64), v(16 cols),
// a, b into smem. 128 threads.
// ---------------------------------------------------------------------------
__device__ __forceinline__ void rec_load2(
    float* sk, float* sq, float* sv, float* sa, float* sb,
    const float* __restrict__ Kn, const float* __restrict__ Q,
    const float* __restrict__ V,
    const float* __restrict__ Al, const float* __restrict__ Be,
    size_t base, size_t abase, int c0, int t0, int tid)
{
    int e   = tid >> 4;          // 0..7
    int vec = (tid & 15) << 2;   // 0..60
    size_t go = base + (size_t)(t0 + e) * DDIM + vec;
    *(float4*)(sk + e * 64 + vec) = *(const float4*)(Kn + go);
    *(float4*)(sq + e * 64 + vec) = *(const float4*)(Q + go);
    if (tid < 32) {
        int ev = tid >> 2;            // 0..7
        int vv = (tid & 3) << 2;      // 0..12
        *(float4*)(sv + ev * 16 + vv) =
            *(const float4*)(V + base + (size_t)(t0 + ev) * DDIM + c0 + vv);
    } else if (tid < 40) {
        int ea = tid - 32;
        sa[ea] = Al[abase + (size_t)(t0 + ea) * HDIM];
    } else if (tid < 48) {
        int eb = tid - 40;
        sb[eb] = Be[abase + (size_t)(t0 + eb) * HDIM];
    }
}

// ---------------------------------------------------------------------------
// Gated delta-rule recurrence, column-split.
// grid = 128: block = bh*4 + cq; block handles columns [cq*16, cq*16+16).
// 128 threads: g = tid&7 (rows g*8..g*8+7, 4 packed pairs), jl = tid>>3.
// u = S^T k, w = S^T q, kq = k.q reduced in one interleaved shfl chain;
// o = a*w + be*err*kq;  S = a*S + (be*err)*k.
// ---------------------------------------------------------------------------
__global__ __launch_bounds__(128) void rec_kernel()
{
    const float* Q  = g_scratch + OF_QN;
    const float* Kn = g_scratch + OF_KN;
    const float* V  = g_scratch + OF_VN;
    const float* Al = g_scratch + OF_A;
    const float* Be = g_scratch + OF_B;
    float*       O  = g_scratch + OF_O;

    int blk = blockIdx.x;
    int bh  = blk >> 2;
    int cq  = blk & 3;
    int c0  = cq * 16;
    int b   = bh >> 4, h = bh & 15;
    const size_t base  = (size_t)b * TDIM * DDIM + (size_t)h * 64;
    const size_t abase = (size_t)b * TDIM * HDIM + h;

    int tid = threadIdx.x;
    int g   = tid & 7;        // row group: rows g*8 .. g*8+7
    int jl  = tid >> 3;       // local column 0..15
    int j   = c0 + jl;
    int r0  = g * 8;

    __shared__ float sk[2][STAGE * 64];
    __shared__ float sq[2][STAGE * 64];
    __shared__ float sv[2][STAGE * 16];
    __shared__ float sa[2][STAGE];
    __shared__ float sb[2][STAGE];

    ull S2[4];
#pragma unroll
    for (int c = 0; c < 4; c++) S2[c] = 0ull;

    rec_load2(sk[0], sq[0], sv[0], sa[0], sb[0], Kn, Q, V, Al, Be,
              base, abase, c0, 0, tid);
    __syncthreads();

    const int nstages = TDIM / STAGE;   // 512
    for (int s = 0; s < nstages; s++) {
        const int buf = s & 1;
        if (s + 1 < nstages) {
            rec_load2(sk[buf ^ 1], sq[buf ^ 1], sv[buf ^ 1], sa[buf ^ 1], sb[buf ^ 1],
                      Kn, Q, V, Al, Be, base, abase, c0, (s + 1) * STAGE, tid);
        }
        const float* kbuf = sk[buf];
        const float* qbuf = sq[buf];
        const float* vbuf = sv[buf];

#pragma unroll
        for (int e = 0; e < STAGE; e++) {
            ull k2[4], q2[4];
            {
                const float* kp = kbuf + e * 64 + r0;
                const float* qp = qbuf + e * 64 + r0;
                *(ulonglong2*)(k2)     = *(const ulonglong2*)(kp);
                *(ulonglong2*)(k2 + 2) = *(const ulonglong2*)(kp + 4);
                *(ulonglong2*)(q2)     = *(const ulonglong2*)(qp);
                *(ulonglong2*)(q2 + 2) = *(const ulonglong2*)(qp + 4);
            }

            ull u2 = 0ull, w2 = 0ull, p2 = 0ull;
#pragma unroll
            for (int c = 0; c < 4; c++) {
                u2 = fma2_(S2[c], k2[c], u2);
                w2 = fma2_(S2[c], q2[c], w2);
                p2 = fma2_(k2[c], q2[c], p2);
            }
            float u  = hadd2_(u2);
            float w  = hadd2_(w2);
            float kq = hadd2_(p2);
            // reduce over the 8 row groups (lane bits 0..2), three values interleaved
#pragma unroll
            for (int off = 1; off <= 4; off <<= 1) {
                u  += __shfl_xor_sync(0xffffffffu, u,  off);
                w  += __shfl_xor_sync(0xffffffffu, w,  off);
                kq += __shfl_xor_sync(0xffffffffu, kq, off);
            }

            float a  = sa[buf][e];
            float bg = sb[buf][e];
            float vj = vbuf[e * 16 + jl];
            float bee = bg * (vj - u);
            float o = fmaf(a, w, bee * kq);

            ull a2  = pack2_(a);
            ull be2 = pack2_(bee);
#pragma unroll
            for (int c = 0; c < 4; c++)
                S2[c] = fma2_(a2, S2[c], mul2_(be2, k2[c]));

            if (g == 0)
                O[base + (size_t)(s * STAGE + e) * DDIM + j] = o;
        }
        __syncthreads();
    }
}

// ---------------------------------------------------------------------------
// RMSNorm (per head, DV=64) * rms_w * output gate g  -> Og
// ---------------------------------------------------------------------------
__global__ __launch_bounds__(512) void post_kernel(const float* __restrict__ rms_w)
{
    const float* O  = g_scratch + OF_O;
    const float* G  = g_scratch + OF_G;
    float*       Og = g_scratch + OF_OG;

    int row  = blockIdx.x;
    int lane = threadIdx.x & 31;
    int h    = threadIdx.x >> 5;
    size_t i0 = (size_t)row * DDIM + h * 64 + lane;

    float v0 = O[i0], v1 = O[i0 + 32];
    float ss = v0 * v0 + v1 * v1;
#pragma unroll
    for (int o = 16; o > 0; o >>= 1) ss += __shfl_xor_sync(0xffffffffu, ss, o);
    float inv = rsqrtf(ss * (1.f / 64.f) + 1e-6f);

    v0 = v0 * inv * rms_w[h * 64 + lane]      * G[i0];
    v1 = v1 * inv * rms_w[h * 64 + lane + 32] * G[i0 + 32];
    Og[i0]      = v0;
    Og[i0 + 32] = v1;
}

// ---------------------------------------------------------------------------
extern "C" void kernel_launch(void* const* d_in, const int* in_sizes, int n_in,
                              void* d_out, int out_size)
{
    (void)in_sizes; (void)n_in; (void)out_size;
    const float* x   = (const float*)d_in[0];
    const float* Wq  = (const float*)d_in[1];
    const float* Wk  = (const float*)d_in[2];
    const float* Wv  = (const float*)d_in[3];
    const float* Wo  = (const float*)d_in[4];
    const float* Wa  = (const float*)d_in[5];
    const float* ba  = (const float*)d_in[6];
    const float* Wb  = (const float*)d_in[7];
    const float* bb  = (const float*)d_in[8];
    const float* Wgd = (const float*)d_in[9];
    const float* Wgu = (const float*)d_in[10];
    const float* rms = (const float*)d_in[11];
    const float* qcw = (const float*)d_in[12];
    const float* qcb = (const float*)d_in[13];
    const float* kcw = (const float*)d_in[14];
    const float* kcb = (const float*)d_in[15];
    const float* vcw = (const float*)d_in[16];
    const float* vcb = (const float*)d_in[17];
    float* out = (float*)d_out;

    dim3 g1024(1024 / 128, MROWS / 128);   // (8, 64)
    dim3 g512 (512 / 128,  MROWS / 128);   // (4, 64)

    // projections
    gemm_kernel<<<g1024, 256>>>(x, 0, Wq, nullptr, OF_Q, MROWS, 1024, 1024, 0);
    gemm_kernel<<<g1024, 256>>>(x, 0, Wk, nullptr, OF_K, MROWS, 1024, 1024, 0);
    gemm_kernel<<<g1024, 256>>>(x, 0, Wv, nullptr, OF_V, MROWS, 1024, 1024, 0);
    // output-gate MLP: silu(x@Wgd) @ Wgu -> sigmoid
    gemm_kernel<<<g512,  256>>>(x, 0, Wgd, nullptr, OF_XG, MROWS, 512, 1024, 1);
    gemm_kernel<<<g1024, 256>>>(nullptr, OF_XG, Wgu, nullptr, OF_G, MROWS, 1024, 512, 2);
    // per-head scalar gates
    ab_kernel<<<MROWS / 8, 256>>>(x, Wa, ba, Wb, bb);
    // causal conv + SiLU (+ L2 norm for q,k), fused q/k/v
    {
        dim3 gc(MROWS, 3);
        conv_kernel<<<gc, 512>>>(qcw, qcb, kcw, kcb, vcw, vcb);
    }
    // sequential delta-rule recurrence (column-split, 4 CTAs per (b,h))
    rec_kernel<<<BDIM * HDIM * 4, 128>>>();
    // RMSNorm + gate
    post_kernel<<<MROWS, 512>>>(rms);
    // final projection
    gemm_kernel<<<g1024, 256>>>(nullptr, OF_OG, Wo, out, 0, MROWS, 1024, 1024, 0);
}

// round 6
// speedup vs baseline: 2.8865x; 1.5344x over previous
#include <cuda_runtime.h>
#include <cuda_bf16.h>

// ---------------------------------------------------------------------------
// GatedDeltaNet  (B=2, T=4096, D=1024, H=16, DK=DV=64, KS=4)
// Round 6 (= round 5 + alignment fixes):
//   - A_STRIDE 10 -> 12 (ldmatrix rows must be 16B-aligned; 40B stride faulted)
//   - __align__(16) on smem tiles
//   - GEMMs on tensor cores: bf16x3 split (Ah*Bh + Ah*Bl + Al*Bh),
//     mma.sync.m16n8k16, fp32 accumulate
// ---------------------------------------------------------------------------

#define TDIM 4096
#define BDIM 2
#define HDIM 16
#define DDIM 1024
#define MROWS (BDIM * TDIM)   // 8192
#define STAGE 8

typedef unsigned long long ull;
typedef unsigned int uint;

static constexpr size_t NM   = (size_t)MROWS * DDIM;          // 8388608
static constexpr size_t OF_Q  = 0;
static constexpr size_t OF_K  = 1 * NM;
static constexpr size_t OF_V  = 2 * NM;
static constexpr size_t OF_QN = 3 * NM;
static constexpr size_t OF_KN = 4 * NM;
static constexpr size_t OF_VN = 5 * NM;
static constexpr size_t OF_G  = 6 * NM;   // output gate g
static constexpr size_t OF_O  = 7 * NM;   // recurrence output
static constexpr size_t OF_OG = 8 * NM;   // gated+normed output
static constexpr size_t OF_XG = 9 * NM;                       // [8192,512]
static constexpr size_t OF_A  = OF_XG + (size_t)MROWS * 512;  // alpha [8192,16]
static constexpr size_t OF_B  = OF_A + (size_t)MROWS * HDIM;  // beta
static constexpr size_t SCRATCH_FLOATS = OF_B + (size_t)MROWS * HDIM;

__device__ float g_scratch[SCRATCH_FLOATS];

__device__ __forceinline__ float sigmoidf_(float x) {
    return 1.f / (1.f + __expf(-x));
}

// ---- f32x2 packed helpers (sm_103a) ---------------------------------------
__device__ __forceinline__ ull fma2_(ull a, ull b, ull c) {
    ull d;
    asm("fma.rn.f32x2 %0, %1, %2, %3;" : "=l"(d) : "l"(a), "l"(b), "l"(c));
    return d;
}
__device__ __forceinline__ ull mul2_(ull a, ull b) {
    ull d;
    asm("mul.rn.f32x2 %0, %1, %2;" : "=l"(d) : "l"(a), "l"(b));
    return d;
}
__device__ __forceinline__ ull pack2_(float x) {
    ull r;
    asm("mov.b64 %0, {%1, %1};" : "=l"(r) : "r"(__float_as_uint(x)));
    return r;
}
__device__ __forceinline__ float hadd2_(ull a) {
    unsigned lo, hi;
    asm("mov.b64 {%0, %1}, %2;" : "=r"(lo), "=r"(hi) : "l"(a));
    return __uint_as_float(lo) + __uint_as_float(hi);
}

// ---- tensor-core helpers ----------------------------------------------------
__device__ __forceinline__ void mma_bf16(float c[4],
    uint a0, uint a1, uint a2, uint a3, uint b0, uint b1)
{
    asm volatile(
        "mma.sync.aligned.m16n8k16.row.col.f32.bf16.bf16.f32 "
        "{%0,%1,%2,%3},{%4,%5,%6,%7},{%8,%9},{%0,%1,%2,%3};"
        : "+f"(c[0]), "+f"(c[1]), "+f"(c[2]), "+f"(c[3])
        : "r"(a0), "r"(a1), "r"(a2), "r"(a3), "r"(b0), "r"(b1));
}
__device__ __forceinline__ void ldsm_x4(uint& r0, uint& r1, uint& r2, uint& r3,
                                        const void* p)
{
    uint a = (uint)__cvta_generic_to_shared(p);
    asm volatile("ldmatrix.sync.aligned.m8n8.x4.shared.b16 {%0,%1,%2,%3},[%4];"
                 : "=r"(r0), "=r"(r1), "=r"(r2), "=r"(r3) : "r"(a));
}
__device__ __forceinline__ void ldsm_x2t(uint& r0, uint& r1, const void* p)
{
    uint a = (uint)__cvta_generic_to_shared(p);
    asm volatile("ldmatrix.sync.aligned.m8n8.x2.trans.shared.b16 {%0,%1},[%2];"
                 : "=r"(r0), "=r"(r1) : "r"(a));
}
// split float4 into bf16 hi-pairs and lo-pairs
__device__ __forceinline__ void split4(float4 v, uint& h01, uint& h23,
                                       uint& l01, uint& l23)
{
    __nv_bfloat162 h01b = __floats2bfloat162_rn(v.x, v.y);
    __nv_bfloat162 h23b = __floats2bfloat162_rn(v.z, v.w);
    float r0 = v.x - __bfloat162float(h01b.x);
    float r1 = v.y - __bfloat162float(h01b.y);
    float r2 = v.z - __bfloat162float(h23b.x);
    float r3 = v.w - __bfloat162float(h23b.y);
    __nv_bfloat162 l01b = __floats2bfloat162_rn(r0, r1);
    __nv_bfloat162 l23b = __floats2bfloat162_rn(r2, r3);
    h01 = *(uint*)&h01b;  h23 = *(uint*)&h23b;
    l01 = *(uint*)&l01b;  l23 = *(uint*)&l23b;
}

// ---------------------------------------------------------------------------
// Tensor-core GEMM: C[M,N] = A[M,K] @ W[K,N], bf16x3 split, fp32 accum.
// Block tile 128x128, k-tile 16, 8 warps (warp tile 64x32), double-buffered.
// act: 0 none, 1 silu, 2 sigmoid.
// ---------------------------------------------------------------------------
#define A_STRIDE 12   // uints per A smem row: 48B, 16B-aligned, conflict-free
#define B_STRIDE 68   // uints per B smem row: 272B = 17*16

__global__ __launch_bounds__(256) void gemm_tc(
    const float* __restrict__ Aext, size_t Aoff,
    const float* __restrict__ W,
    float* __restrict__ Cext, size_t Coff,
    int M, int N, int K, int act)
{
    const float* A = Aext ? Aext : (const float*)g_scratch + Aoff;
    float*       C = Cext ? Cext : g_scratch + Coff;

    __shared__ __align__(16) uint As[2][2][128][A_STRIDE];  // [buf][hi/lo][m][k-pairs]
    __shared__ __align__(16) uint Bs[2][2][16][B_STRIDE];   // [buf][hi/lo][k][n-pairs]

    const int tid  = threadIdx.x;
    const int brow = blockIdx.y * 128;
    const int bcol = blockIdx.x * 128;

    const int lane = tid & 31;
    const int warp = tid >> 5;
    const int wm   = warp >> 2;      // 0..1
    const int wn   = warp & 3;       // 0..3
    const int gid  = lane >> 2;
    const int tig  = lane & 3;

    // loader indexing
    const int am0 = tid >> 2;              // 0..63 (+64 second)
    const int ak0 = (tid & 3) << 2;        // 0,4,8,12
    const int bk0 = tid >> 5;              // 0..7  (+8 second)
    const int bn0 = (tid & 31) << 2;       // 0..124

    const float* ApA = A + (size_t)(brow + am0) * K + ak0;
    const float* ApB = ApA + (size_t)64 * K;
    const float* BpA = W + (size_t)bk0 * N + bcol + bn0;
    const float* BpB = BpA + (size_t)8 * N;

    float acc[4][4][4];
#pragma unroll
    for (int i = 0; i < 4; i++)
#pragma unroll
        for (int j = 0; j < 4; j++)
#pragma unroll
            for (int c = 0; c < 4; c++) acc[i][j][c] = 0.f;

    // ldmatrix source addressing (per lane)
    const int a_lrow = lane & 15;
    const int a_koff = (lane >> 4) * 4;     // uints (16B)
    const int b_lrow = lane & 15;

    float4 avA, avB, bvA, bvB;

    // prologue: tile 0
    avA = *(const float4*)(ApA);
    avB = *(const float4*)(ApB);
    bvA = *(const float4*)(BpA);
    bvB = *(const float4*)(BpB);
    {
        uint h01, h23, l01, l23;
        split4(avA, h01, h23, l01, l23);
        *(uint2*)&As[0][0][am0][ak0 >> 1]      = make_uint2(h01, h23);
        *(uint2*)&As[0][1][am0][ak0 >> 1]      = make_uint2(l01, l23);
        split4(avB, h01, h23, l01, l23);
        *(uint2*)&As[0][0][am0 + 64][ak0 >> 1] = make_uint2(h01, h23);
        *(uint2*)&As[0][1][am0 + 64][ak0 >> 1] = make_uint2(l01, l23);
        split4(bvA, h01, h23, l01, l23);
        *(uint2*)&Bs[0][0][bk0][bn0 >> 1]      = make_uint2(h01, h23);
        *(uint2*)&Bs[0][1][bk0][bn0 >> 1]      = make_uint2(l01, l23);
        split4(bvB, h01, h23, l01, l23);
        *(uint2*)&Bs[0][0][bk0 + 8][bn0 >> 1]  = make_uint2(h01, h23);
        *(uint2*)&Bs[0][1][bk0 + 8][bn0 >> 1]  = make_uint2(l01, l23);
    }
    __syncthreads();

    const int nk = K >> 4;
    for (int kt = 0; kt < nk; kt++) {
        const int buf = kt & 1;
        if (kt + 1 < nk) {
            const int ko = (kt + 1) << 4;
            avA = *(const float4*)(ApA + ko);
            avB = *(const float4*)(ApB + ko);
            bvA = *(const float4*)(BpA + (size_t)ko * N);
            bvB = *(const float4*)(BpB + (size_t)ko * N);
        }

        // load fragments
        uint Ah[4][4], Al[4][4], Bh[4][2], Bl[4][2];
#pragma unroll
        for (int mt = 0; mt < 4; mt++) {
            int row = wm * 64 + mt * 16 + a_lrow;
            ldsm_x4(Ah[mt][0], Ah[mt][1], Ah[mt][2], Ah[mt][3],
                    &As[buf][0][row][a_koff]);
            ldsm_x4(Al[mt][0], Al[mt][1], Al[mt][2], Al[mt][3],
                    &As[buf][1][row][a_koff]);
        }
#pragma unroll
        for (int nt = 0; nt < 4; nt++) {
            int nu = wn * 16 + nt * 4;   // uint offset within row (16B units)
            ldsm_x2t(Bh[nt][0], Bh[nt][1], &Bs[buf][0][b_lrow][nu]);
            ldsm_x2t(Bl[nt][0], Bl[nt][1], &Bs[buf][1][b_lrow][nu]);
        }

#pragma unroll
        for (int mt = 0; mt < 4; mt++) {
#pragma unroll
            for (int nt = 0; nt < 4; nt++) {
                mma_bf16(acc[mt][nt], Ah[mt][0], Ah[mt][1], Ah[mt][2], Ah[mt][3],
                         Bh[nt][0], Bh[nt][1]);
                mma_bf16(acc[mt][nt], Ah[mt][0], Ah[mt][1], Ah[mt][2], Ah[mt][3],
                         Bl[nt][0], Bl[nt][1]);
                mma_bf16(acc[mt][nt], Al[mt][0], Al[mt][1], Al[mt][2], Al[mt][3],
                         Bh[nt][0], Bh[nt][1]);
            }
        }

        if (kt + 1 < nk) {
            const int nb = buf ^ 1;
            uint h01, h23, l01, l23;
            split4(avA, h01, h23, l01, l23);
            *(uint2*)&As[nb][0][am0][ak0 >> 1]      = make_uint2(h01, h23);
            *(uint2*)&As[nb][1][am0][ak0 >> 1]      = make_uint2(l01, l23);
            split4(avB, h01, h23, l01, l23);
            *(uint2*)&As[nb][0][am0 + 64][ak0 >> 1] = make_uint2(h01, h23);
            *(uint2*)&As[nb][1][am0 + 64][ak0 >> 1] = make_uint2(l01, l23);
            split4(bvA, h01, h23, l01, l23);
            *(uint2*)&Bs[nb][0][bk0][bn0 >> 1]      = make_uint2(h01, h23);
            *(uint2*)&Bs[nb][1][bk0][bn0 >> 1]      = make_uint2(l01, l23);
            split4(bvB, h01, h23, l01, l23);
            *(uint2*)&Bs[nb][0][bk0 + 8][bn0 >> 1]  = make_uint2(h01, h23);
            *(uint2*)&Bs[nb][1][bk0 + 8][bn0 >> 1]  = make_uint2(l01, l23);
            __syncthreads();
        }
    }

    // epilogue
#pragma unroll
    for (int mt = 0; mt < 4; mt++) {
        int row0 = brow + wm * 64 + mt * 16 + gid;
#pragma unroll
        for (int nt = 0; nt < 4; nt++) {
            int col0 = bcol + wn * 32 + nt * 8 + 2 * tig;
            float c0 = acc[mt][nt][0], c1 = acc[mt][nt][1];
            float c2 = acc[mt][nt][2], c3 = acc[mt][nt][3];
            if (act == 1) {
                c0 *= sigmoidf_(c0); c1 *= sigmoidf_(c1);
                c2 *= sigmoidf_(c2); c3 *= sigmoidf_(c3);
            } else if (act == 2) {
                c0 = sigmoidf_(c0); c1 = sigmoidf_(c1);
                c2 = sigmoidf_(c2); c3 = sigmoidf_(c3);
            }
            *(float2*)(C + (size_t)row0 * N + col0)       = make_float2(c0, c1);
            *(float2*)(C + (size_t)(row0 + 8) * N + col0) = make_float2(c2, c3);
        }
    }
}

// ---------------------------------------------------------------------------
// alpha/beta gates: 8 warps per block, 1 warp per row; lane<16 -> alpha.
// ---------------------------------------------------------------------------
__global__ __launch_bounds__(256) void ab_kernel(
    const float* __restrict__ x,
    const float* __restrict__ Wa, const float* __restrict__ ba,
    const float* __restrict__ Wb, const float* __restrict__ bb)
{
    int row  = blockIdx.x * 8 + (threadIdx.x >> 5);
    int lane = threadIdx.x & 31;
    const float* xr = x + (size_t)row * DDIM;
    const float* W  = (lane < 16) ? Wa : Wb;
    int h = lane & 15;

    float s0 = 0.f, s1 = 0.f, s2 = 0.f, s3 = 0.f;
#pragma unroll 4
    for (int i = 0; i < DDIM; i += 4) {
        s0 = fmaf(xr[i + 0], W[(i + 0) * HDIM + h], s0);
        s1 = fmaf(xr[i + 1], W[(i + 1) * HDIM + h], s1);
        s2 = fmaf(xr[i + 2], W[(i + 2) * HDIM + h], s2);
        s3 = fmaf(xr[i + 3], W[(i + 3) * HDIM + h], s3);
    }
    float s = (s0 + s1) + (s2 + s3);
    if (lane < 16) {
        float sg = sigmoidf_(s + ba[h]);
        g_scratch[OF_A + (size_t)row * HDIM + h] = fminf(fmaxf(sg, 0.1f), 1.0f);
    } else {
        float sg = sigmoidf_(s + bb[h]);
        g_scratch[OF_B + (size_t)row * HDIM + h] = fminf(sg, 1.0f);
    }
}

// ---------------------------------------------------------------------------
// Causal depthwise conv (K=4) + SiLU (+ L2 norm for q,k). blockIdx.y selects.
// ---------------------------------------------------------------------------
__global__ __launch_bounds__(512) void conv_kernel(
    const float* __restrict__ qcw, const float* __restrict__ qcb,
    const float* __restrict__ kcw, const float* __restrict__ kcb,
    const float* __restrict__ vcw, const float* __restrict__ vcb)
{
    int which = blockIdx.y;
    const float* w;
    const float* bias;
    size_t pre_off, out_off;
    int do_norm;
    if (which == 0) { w = qcw; bias = qcb; pre_off = OF_Q; out_off = OF_QN; do_norm = 1; }
    else if (which == 1) { w = kcw; bias = kcb; pre_off = OF_K; out_off = OF_KN; do_norm = 1; }
    else { w = vcw; bias = vcb; pre_off = OF_V; out_off = OF_VN; do_norm = 0; }

    const float* pre = (const float*)g_scratch + pre_off;
    float*       out = g_scratch + out_off;

    int row  = blockIdx.x;
    int t    = row & (TDIM - 1);
    int lane = threadIdx.x & 31;
    int h    = threadIdx.x >> 5;
    int c0   = h * 64 + lane;
    int c1   = c0 + 32;

    const float* p = pre + (size_t)row * DDIM;
    float v0 = bias[c0], v1 = bias[c1];
#pragma unroll
    for (int kk = 0; kk < 4; kk++) {
        int dt = kk - 3;
        if (t + dt >= 0) {
            const float* pr = p + (ptrdiff_t)dt * DDIM;
            v0 = fmaf(w[c0 * 4 + kk], pr[c0], v0);
            v1 = fmaf(w[c1 * 4 + kk], pr[c1], v1);
        }
    }
    v0 *= sigmoidf_(v0);   // SiLU
    v1 *= sigmoidf_(v1);

    if (do_norm) {
        float ss = v0 * v0 + v1 * v1;
#pragma unroll
        for (int o = 16; o > 0; o >>= 1) ss += __shfl_xor_sync(0xffffffffu, ss, o);
        float inv = 1.f / fmaxf(sqrtf(ss), 1e-6f);
        v0 *= inv; v1 *= inv;
    }
    out[(size_t)row * DDIM + c0] = v0;
    out[(size_t)row * DDIM + c1] = v1;
}

// ---------------------------------------------------------------------------
// Recurrence stage loader.
// ---------------------------------------------------------------------------
__device__ __forceinline__ void rec_load2(
    float* sk, float* sq, float* sv, float* sa, float* sb,
    const float* __restrict__ Kn, const float* __restrict__ Q,
    const float* __restrict__ V,
    const float* __restrict__ Al, const float* __restrict__ Be,
    size_t base, size_t abase, int c0, int t0, int tid)
{
    int e   = tid >> 4;          // 0..7
    int vec = (tid & 15) << 2;   // 0..60
    size_t go = base + (size_t)(t0 + e) * DDIM + vec;
    *(float4*)(sk + e * 64 + vec) = *(const float4*)(Kn + go);
    *(float4*)(sq + e * 64 + vec) = *(const float4*)(Q + go);
    if (tid < 32) {
        int ev = tid >> 2;
        int vv = (tid & 3) << 2;
        *(float4*)(sv + ev * 16 + vv) =
            *(const float4*)(V + base + (size_t)(t0 + ev) * DDIM + c0 + vv);
    } else if (tid < 40) {
        int ea = tid - 32;
        sa[ea] = Al[abase + (size_t)(t0 + ea) * HDIM];
    } else if (tid < 48) {
        int eb = tid - 40;
        sb[eb] = Be[abase + (size_t)(t0 + eb) * HDIM];
    }
}

// ---------------------------------------------------------------------------
// Gated delta-rule recurrence, column-split (4 CTAs per (b,h)).
// ---------------------------------------------------------------------------
__global__ __launch_bounds__(128) void rec_kernel()
{
    const float* Q  = g_scratch + OF_QN;
    const float* Kn = g_scratch + OF_KN;
    const float* V  = g_scratch + OF_VN;
    const float* Al = g_scratch + OF_A;
    const float* Be = g_scratch + OF_B;
    float*       O  = g_scratch + OF_O;

    int blk = blockIdx.x;
    int bh  = blk >> 2;
    int cq  = blk & 3;
    int c0  = cq * 16;
    int b   = bh >> 4, h = bh & 15;
    const size_t base  = (size_t)b * TDIM * DDIM + (size_t)h * 64;
    const size_t abase = (size_t)b * TDIM * HDIM + h;

    int tid = threadIdx.x;
    int g   = tid & 7;
    int jl  = tid >> 3;
    int j   = c0 + jl;
    int r0  = g * 8;

    __shared__ __align__(16) float sk[2][STAGE * 64];
    __shared__ __align__(16) float sq[2][STAGE * 64];
    __shared__ __align__(16) float sv[2][STAGE * 16];
    __shared__ float sa[2][STAGE];
    __shared__ float sb[2][STAGE];

    ull S2[4];
#pragma unroll
    for (int c = 0; c < 4; c++) S2[c] = 0ull;

    rec_load2(sk[0], sq[0], sv[0], sa[0], sb[0], Kn, Q, V, Al, Be,
              base, abase, c0, 0, tid);
    __syncthreads();

    const int nstages = TDIM / STAGE;
    for (int s = 0; s < nstages; s++) {
        const int buf = s & 1;
        if (s + 1 < nstages) {
            rec_load2(sk[buf ^ 1], sq[buf ^ 1], sv[buf ^ 1], sa[buf ^ 1], sb[buf ^ 1],
                      Kn, Q, V, Al, Be, base, abase, c0, (s + 1) * STAGE, tid);
        }
        const float* kbuf = sk[buf];
        const float* qbuf = sq[buf];
        const float* vbuf = sv[buf];

#pragma unroll
        for (int e = 0; e < STAGE; e++) {
            ull k2[4], q2[4];
            {
                const float* kp = kbuf + e * 64 + r0;
                const float* qp = qbuf + e * 64 + r0;
                *(ulonglong2*)(k2)     = *(const ulonglong2*)(kp);
                *(ulonglong2*)(k2 + 2) = *(const ulonglong2*)(kp + 4);
                *(ulonglong2*)(q2)     = *(const ulonglong2*)(qp);
                *(ulonglong2*)(q2 + 2) = *(const ulonglong2*)(qp + 4);
            }

            ull u2 = 0ull, w2 = 0ull, p2 = 0ull;
#pragma unroll
            for (int c = 0; c < 4; c++) {
                u2 = fma2_(S2[c], k2[c], u2);
                w2 = fma2_(S2[c], q2[c], w2);
                p2 = fma2_(k2[c], q2[c], p2);
            }
            float u  = hadd2_(u2);
            float w  = hadd2_(w2);
            float kq = hadd2_(p2);
#pragma unroll
            for (int off = 1; off <= 4; off <<= 1) {
                u  += __shfl_xor_sync(0xffffffffu, u,  off);
                w  += __shfl_xor_sync(0xffffffffu, w,  off);
                kq += __shfl_xor_sync(0xffffffffu, kq, off);
            }

            float a  = sa[buf][e];
            float bg = sb[buf][e];
            float vj = vbuf[e * 16 + jl];
            float bee = bg * (vj - u);
            float o = fmaf(a, w, bee * kq);

            ull a2  = pack2_(a);
            ull be2 = pack2_(bee);
#pragma unroll
            for (int c = 0; c < 4; c++)
                S2[c] = fma2_(a2, S2[c], mul2_(be2, k2[c]));

            if (g == 0)
                O[base + (size_t)(s * STAGE + e) * DDIM + j] = o;
        }
        __syncthreads();
    }
}

// ---------------------------------------------------------------------------
// RMSNorm (per head, DV=64) * rms_w * output gate g  -> Og
// ---------------------------------------------------------------------------
__global__ __launch_bounds__(512) void post_kernel(const float* __restrict__ rms_w)
{
    const float* O  = g_scratch + OF_O;
    const float* G  = g_scratch + OF_G;
    float*       Og = g_scratch + OF_OG;

    int row  = blockIdx.x;
    int lane = threadIdx.x & 31;
    int h    = threadIdx.x >> 5;
    size_t i0 = (size_t)row * DDIM + h * 64 + lane;

    float v0 = O[i0], v1 = O[i0 + 32];
    float ss = v0 * v0 + v1 * v1;
#pragma unroll
    for (int o = 16; o > 0; o >>= 1) ss += __shfl_xor_sync(0xffffffffu, ss, o);
    float inv = rsqrtf(ss * (1.f / 64.f) + 1e-6f);

    v0 = v0 * inv * rms_w[h * 64 + lane]      * G[i0];
    v1 = v1 * inv * rms_w[h * 64 + lane + 32] * G[i0 + 32];
    Og[i0]      = v0;
    Og[i0 + 32] = v1;
}

// ---------------------------------------------------------------------------
extern "C" void kernel_launch(void* const* d_in, const int* in_sizes, int n_in,
                              void* d_out, int out_size)
{
    (void)in_sizes; (void)n_in; (void)out_size;
    const float* x   = (const float*)d_in[0];
    const float* Wq  = (const float*)d_in[1];
    const float* Wk  = (const float*)d_in[2];
    const float* Wv  = (const float*)d_in[3];
    const float* Wo  = (const float*)d_in[4];
    const float* Wa  = (const float*)d_in[5];
    const float* ba  = (const float*)d_in[6];
    const float* Wb  = (const float*)d_in[7];
    const float* bb  = (const float*)d_in[8];
    const float* Wgd = (const float*)d_in[9];
    const float* Wgu = (const float*)d_in[10];
    const float* rms = (const float*)d_in[11];
    const float* qcw = (const float*)d_in[12];
    const float* qcb = (const float*)d_in[13];
    const float* kcw = (const float*)d_in[14];
    const float* kcb = (const float*)d_in[15];
    const float* vcw = (const float*)d_in[16];
    const float* vcb = (const float*)d_in[17];
    float* out = (float*)d_out;

    dim3 g1024(1024 / 128, MROWS / 128);   // (8, 64)
    dim3 g512 (512 / 128,  MROWS / 128);   // (4, 64)

    // projections (tensor cores, bf16x3)
    gemm_tc<<<g1024, 256>>>(x, 0, Wq, nullptr, OF_Q, MROWS, 1024, 1024, 0);
    gemm_tc<<<g1024, 256>>>(x, 0, Wk, nullptr, OF_K, MROWS, 1024, 1024, 0);
    gemm_tc<<<g1024, 256>>>(x, 0, Wv, nullptr, OF_V, MROWS, 1024, 1024, 0);
    // output-gate MLP: silu(x@Wgd) @ Wgu -> sigmoid
    gemm_tc<<<g512,  256>>>(x, 0, Wgd, nullptr, OF_XG, MROWS, 512, 1024, 1);
    gemm_tc<<<g1024, 256>>>(nullptr, OF_XG, Wgu, nullptr, OF_G, MROWS, 1024, 512, 2);
    // per-head scalar gates
    ab_kernel<<<MROWS / 8, 256>>>(x, Wa, ba, Wb, bb);
    // causal conv + SiLU (+ L2 norm for q,k), fused q/k/v
    {
        dim3 gc(MROWS, 3);
        conv_kernel<<<gc, 512>>>(qcw, qcb, kcw, kcb, vcw, vcb);
    }
    // sequential delta-rule recurrence (column-split, 4 CTAs per (b,h))
    rec_kernel<<<BDIM * HDIM * 4, 128>>>();
    // RMSNorm + gate
    post_kernel<<<MROWS, 512>>>(rms);
    // final projection
    gemm_tc<<<g1024, 256>>>(nullptr, OF_OG, Wo, out, 0, MROWS, 1024, 1024, 0);
}

// round 7
// speedup vs baseline: 2.9169x; 1.0105x over previous
#include <cuda_runtime.h>
#include <cuda_bf16.h>

// ---------------------------------------------------------------------------
// GatedDeltaNet  (B=2, T=4096, D=1024, H=16, DK=DV=64, KS=4)
// Round 6 (= round 5 + alignment fixes):
//   - A_STRIDE 10 -> 12 (ldmatrix rows must be 16B-aligned; 40B stride faulted)
//   - __align__(16) on smem tiles
//   - GEMMs on tensor cores: bf16x3 split (Ah*Bh + Ah*Bl + Al*Bh),
//     mma.sync.m16n8k16, fp32 accumulate
// ---------------------------------------------------------------------------

#define TDIM 4096
#define BDIM 2
#define HDIM 16
#define DDIM 1024
#define MROWS (BDIM * TDIM)   // 8192
#define STAGE 8

typedef unsigned long long ull;
typedef unsigned int uint;

static constexpr size_t NM   = (size_t)MROWS * DDIM;          // 8388608
static constexpr size_t OF_Q  = 0;
static constexpr size_t OF_K  = 1 * NM;
static constexpr size_t OF_V  = 2 * NM;
static constexpr size_t OF_QN = 3 * NM;
static constexpr size_t OF_KN = 4 * NM;
static constexpr size_t OF_VN = 5 * NM;
static constexpr size_t OF_G  = 6 * NM;   // output gate g
static constexpr size_t OF_O  = 7 * NM;   // recurrence output
static constexpr size_t OF_OG = 8 * NM;   // gated+normed output
static constexpr size_t OF_XG = 9 * NM;                       // [8192,512]
static constexpr size_t OF_A  = OF_XG + (size_t)MROWS * 512;  // alpha [8192,16]
static constexpr size_t OF_B  = OF_A + (size_t)MROWS * HDIM;  // beta
static constexpr size_t SCRATCH_FLOATS = OF_B + (size_t)MROWS * HDIM;

__device__ float g_scratch[SCRATCH_FLOATS];

__device__ __forceinline__ float sigmoidf_(float x) {
    return 1.f / (1.f + __expf(-x));
}

// ---- f32x2 packed helpers (sm_103a) ---------------------------------------
__device__ __forceinline__ ull fma2_(ull a, ull b, ull c) {
    ull d;
    asm("fma.rn.f32x2 %0, %1, %2, %3;" : "=l"(d) : "l"(a), "l"(b), "l"(c));
    return d;
}
__device__ __forceinline__ ull mul2_(ull a, ull b) {
    ull d;
    asm("mul.rn.f32x2 %0, %1, %2;" : "=l"(d) : "l"(a), "l"(b));
    return d;
}
__device__ __forceinline__ ull pack2_(float x) {
    ull r;
    asm("mov.b64 %0, {%1, %1};" : "=l"(r) : "r"(__float_as_uint(x)));
    return r;
}
__device__ __forceinline__ float hadd2_(ull a) {
    unsigned lo, hi;
    asm("mov.b64 {%0, %1}, %2;" : "=r"(lo), "=r"(hi) : "l"(a));
    return __uint_as_float(lo) + __uint_as_float(hi);
}

// ---- tensor-core helpers ----------------------------------------------------
__device__ __forceinline__ void mma_bf16(float c[4],
    uint a0, uint a1, uint a2, uint a3, uint b0, uint b1)
{
    asm volatile(
        "mma.sync.aligned.m16n8k16.row.col.f32.bf16.bf16.f32 "
        "{%0,%1,%2,%3},{%4,%5,%6,%7},{%8,%9},{%0,%1,%2,%3};"
        : "+f"(c[0]), "+f"(c[1]), "+f"(c[2]), "+f"(c[3])
        : "r"(a0), "r"(a1), "r"(a2), "r"(a3), "r"(b0), "r"(b1));
}
__device__ __forceinline__ void ldsm_x4(uint& r0, uint& r1, uint& r2, uint& r3,
                                        const void* p)
{
    uint a = (uint)__cvta_generic_to_shared(p);
    asm volatile("ldmatrix.sync.aligned.m8n8.x4.shared.b16 {%0,%1,%2,%3},[%4];"
                 : "=r"(r0), "=r"(r1), "=r"(r2), "=r"(r3) : "r"(a));
}
__device__ __forceinline__ void ldsm_x2t(uint& r0, uint& r1, const void* p)
{
    uint a = (uint)__cvta_generic_to_shared(p);
    asm volatile("ldmatrix.sync.aligned.m8n8.x2.trans.shared.b16 {%0,%1},[%2];"
                 : "=r"(r0), "=r"(r1) : "r"(a));
}
// split float4 into bf16 hi-pairs and lo-pairs
__device__ __forceinline__ void split4(float4 v, uint& h01, uint& h23,
                                       uint& l01, uint& l23)
{
    __nv_bfloat162 h01b = __floats2bfloat162_rn(v.x, v.y);
    __nv_bfloat162 h23b = __floats2bfloat162_rn(v.z, v.w);
    float r0 = v.x - __bfloat162float(h01b.x);
    float r1 = v.y - __bfloat162float(h01b.y);
    float r2 = v.z - __bfloat162float(h23b.x);
    float r3 = v.w - __bfloat162float(h23b.y);
    __nv_bfloat162 l01b = __floats2bfloat162_rn(r0, r1);
    __nv_bfloat162 l23b = __floats2bfloat162_rn(r2, r3);
    h01 = *(uint*)&h01b;  h23 = *(uint*)&h23b;
    l01 = *(uint*)&l01b;  l23 = *(uint*)&l23b;
}

// ---------------------------------------------------------------------------
// Tensor-core GEMM: C[M,N] = A[M,K] @ W[K,N], bf16x3 split, fp32 accum.
// Block tile 128x128, k-tile 16, 8 warps (warp tile 64x32), double-buffered.
// act: 0 none, 1 silu, 2 sigmoid.
// ---------------------------------------------------------------------------
#define A_STRIDE 12   // uints per A smem row: 48B, 16B-aligned, conflict-free
#define B_STRIDE 68   // uints per B smem row: 272B = 17*16

__global__ __launch_bounds__(256) void gemm_tc(
    const float* __restrict__ Aext, size_t Aoff,
    const float* __restrict__ W,
    float* __restrict__ Cext, size_t Coff,
    int M, int N, int K, int act)
{
    const float* A = Aext ? Aext : (const float*)g_scratch + Aoff;
    float*       C = Cext ? Cext : g_scratch + Coff;

    __shared__ __align__(16) uint As[2][2][128][A_STRIDE];  // [buf][hi/lo][m][k-pairs]
    __shared__ __align__(16) uint Bs[2][2][16][B_STRIDE];   // [buf][hi/lo][k][n-pairs]

    const int tid  = threadIdx.x;
    const int brow = blockIdx.y * 128;
    const int bcol = blockIdx.x * 128;

    const int lane = tid & 31;
    const int warp = tid >> 5;
    const int wm   = warp >> 2;      // 0..1
    const int wn   = warp & 3;       // 0..3
    const int gid  = lane >> 2;
    const int tig  = lane & 3;

    // loader indexing
    const int am0 = tid >> 2;              // 0..63 (+64 second)
    const int ak0 = (tid & 3) << 2;        // 0,4,8,12
    const int bk0 = tid >> 5;              // 0..7  (+8 second)
    const int bn0 = (tid & 31) << 2;       // 0..124

    const float* ApA = A + (size_t)(brow + am0) * K + ak0;
    const float* ApB = ApA + (size_t)64 * K;
    const float* BpA = W + (size_t)bk0 * N + bcol + bn0;
    const float* BpB = BpA + (size_t)8 * N;

    float acc[4][4][4];
#pragma unroll
    for (int i = 0; i < 4; i++)
#pragma unroll
        for (int j = 0; j < 4; j++)
#pragma unroll
            for (int c = 0; c < 4; c++) acc[i][j][c] = 0.f;

    // ldmatrix source addressing (per lane)
    const int a_lrow = lane & 15;
    const int a_koff = (lane >> 4) * 4;     // uints (16B)
    const int b_lrow = lane & 15;

    float4 avA, avB, bvA, bvB;

    // prologue: tile 0
    avA = *(const float4*)(ApA);
    avB = *(const float4*)(ApB);
    bvA = *(const float4*)(BpA);
    bvB = *(const float4*)(BpB);
    {
        uint h01, h23, l01, l23;
        split4(avA, h01, h23, l01, l23);
        *(uint2*)&As[0][0][am0][ak0 >> 1]      = make_uint2(h01, h23);
        *(uint2*)&As[0][1][am0][ak0 >> 1]      = make_uint2(l01, l23);
        split4(avB, h01, h23, l01, l23);
        *(uint2*)&As[0][0][am0 + 64][ak0 >> 1] = make_uint2(h01, h23);
        *(uint2*)&As[0][1][am0 + 64][ak0 >> 1] = make_uint2(l01, l23);
        split4(bvA, h01, h23, l01, l23);
        *(uint2*)&Bs[0][0][bk0][bn0 >> 1]      = make_uint2(h01, h23);
        *(uint2*)&Bs[0][1][bk0][bn0 >> 1]      = make_uint2(l01, l23);
        split4(bvB, h01, h23, l01, l23);
        *(uint2*)&Bs[0][0][bk0 + 8][bn0 >> 1]  = make_uint2(h01, h23);
        *(uint2*)&Bs[0][1][bk0 + 8][bn0 >> 1]  = make_uint2(l01, l23);
    }
    __syncthreads();

    const int nk = K >> 4;
    for (int kt = 0; kt < nk; kt++) {
        const int buf = kt & 1;
        if (kt + 1 < nk) {
            const int ko = (kt + 1) << 4;
            avA = *(const float4*)(ApA + ko);
            avB = *(const float4*)(ApB + ko);
            bvA = *(const float4*)(BpA + (size_t)ko * N);
            bvB = *(const float4*)(BpB + (size_t)ko * N);
        }

        // load fragments
        uint Ah[4][4], Al[4][4], Bh[4][2], Bl[4][2];
#pragma unroll
        for (int mt = 0; mt < 4; mt++) {
            int row = wm * 64 + mt * 16 + a_lrow;
            ldsm_x4(Ah[mt][0], Ah[mt][1], Ah[mt][2], Ah[mt][3],
                    &As[buf][0][row][a_koff]);
            ldsm_x4(Al[mt][0], Al[mt][1], Al[mt][2], Al[mt][3],
                    &As[buf][1][row][a_koff]);
        }
#pragma unroll
        for (int nt = 0; nt < 4; nt++) {
            int nu = wn * 16 + nt * 4;   // uint offset within row (16B units)
            ldsm_x2t(Bh[nt][0], Bh[nt][1], &Bs[buf][0][b_lrow][nu]);
            ldsm_x2t(Bl[nt][0], Bl[nt][1], &Bs[buf][1][b_lrow][nu]);
        }

#pragma unroll
        for (int mt = 0; mt < 4; mt++) {
#pragma unroll
            for (int nt = 0; nt < 4; nt++) {
                mma_bf16(acc[mt][nt], Ah[mt][0], Ah[mt][1], Ah[mt][2], Ah[mt][3],
                         Bh[nt][0], Bh[nt][1]);
                mma_bf16(acc[mt][nt], Ah[mt][0], Ah[mt][1], Ah[mt][2], Ah[mt][3],
                         Bl[nt][0], Bl[nt][1]);
                mma_bf16(acc[mt][nt], Al[mt][0], Al[mt][1], Al[mt][2], Al[mt][3],
                         Bh[nt][0], Bh[nt][1]);
            }
        }

        if (kt + 1 < nk) {
            const int nb = buf ^ 1;
            uint h01, h23, l01, l23;
            split4(avA, h01, h23, l01, l23);
            *(uint2*)&As[nb][0][am0][ak0 >> 1]      = make_uint2(h01, h23);
            *(uint2*)&As[nb][1][am0][ak0 >> 1]      = make_uint2(l01, l23);
            split4(avB, h01, h23, l01, l23);
            *(uint2*)&As[nb][0][am0 + 64][ak0 >> 1] = make_uint2(h01, h23);
            *(uint2*)&As[nb][1][am0 + 64][ak0 >> 1] = make_uint2(l01, l23);
            split4(bvA, h01, h23, l01, l23);
            *(uint2*)&Bs[nb][0][bk0][bn0 >> 1]      = make_uint2(h01, h23);
            *(uint2*)&Bs[nb][1][bk0][bn0 >> 1]      = make_uint2(l01, l23);
            split4(bvB, h01, h23, l01, l23);
            *(uint2*)&Bs[nb][0][bk0 + 8][bn0 >> 1]  = make_uint2(h01, h23);
            *(uint2*)&Bs[nb][1][bk0 + 8][bn0 >> 1]  = make_uint2(l01, l23);
            __syncthreads();
        }
    }

    // epilogue
#pragma unroll
    for (int mt = 0; mt < 4; mt++) {
        int row0 = brow + wm * 64 + mt * 16 + gid;
#pragma unroll
        for (int nt = 0; nt < 4; nt++) {
            int col0 = bcol + wn * 32 + nt * 8 + 2 * tig;
            float c0 = acc[mt][nt][0], c1 = acc[mt][nt][1];
            float c2 = acc[mt][nt][2], c3 = acc[mt][nt][3];
            if (act == 1) {
                c0 *= sigmoidf_(c0); c1 *= sigmoidf_(c1);
                c2 *= sigmoidf_(c2); c3 *= sigmoidf_(c3);
            } else if (act == 2) {
                c0 = sigmoidf_(c0); c1 = sigmoidf_(c1);
                c2 = sigmoidf_(c2); c3 = sigmoidf_(c3);
            }
            *(float2*)(C + (size_t)row0 * N + col0)       = make_float2(c0, c1);
            *(float2*)(C + (size_t)(row0 + 8) * N + col0) = make_float2(c2, c3);
        }
    }
}

// ---------------------------------------------------------------------------
// alpha/beta gates: 8 warps per block, 1 warp per row; lane<16 -> alpha.
// ---------------------------------------------------------------------------
__global__ __launch_bounds__(256) void ab_kernel(
    const float* __restrict__ x,
    const float* __restrict__ Wa, const float* __restrict__ ba,
    const float* __restrict__ Wb, const float* __restrict__ bb)
{
    int row  = blockIdx.x * 8 + (threadIdx.x >> 5);
    int lane = threadIdx.x & 31;
    const float* xr = x + (size_t)row * DDIM;
    const float* W  = (lane < 16) ? Wa : Wb;
    int h = lane & 15;

    float s0 = 0.f, s1 = 0.f, s2 = 0.f, s3 = 0.f;
#pragma unroll 4
    for (int i = 0; i < DDIM; i += 4) {
        s0 = fmaf(xr[i + 0], W[(i + 0) * HDIM + h], s0);
        s1 = fmaf(xr[i + 1], W[(i + 1) * HDIM + h], s1);
        s2 = fmaf(xr[i + 2], W[(i + 2) * HDIM + h], s2);
        s3 = fmaf(xr[i + 3], W[(i + 3) * HDIM + h], s3);
    }
    float s = (s0 + s1) + (s2 + s3);
    if (lane < 16) {
        float sg = sigmoidf_(s + ba[h]);
        g_scratch[OF_A + (size_t)row * HDIM + h] = fminf(fmaxf(sg, 0.1f), 1.0f);
    } else {
        float sg = sigmoidf_(s + bb[h]);
        g_scratch[OF_B + (size_t)row * HDIM + h] = fminf(sg, 1.0f);
    }
}

// ---------------------------------------------------------------------------
// Causal depthwise conv (K=4) + SiLU (+ L2 norm for q,k). blockIdx.y selects.
// ---------------------------------------------------------------------------
__global__ __launch_bounds__(512) void conv_kernel(
    const float* __restrict__ qcw, const float* __restrict__ qcb,
    const float* __restrict__ kcw, const float* __restrict__ kcb,
    const float* __restrict__ vcw, const float* __restrict__ vcb)
{
    int which = blockIdx.y;
    const float* w;
    const float* bias;
    size_t pre_off, out_off;
    int do_norm;
    if (which == 0) { w = qcw; bias = qcb; pre_off = OF_Q; out_off = OF_QN; do_norm = 1; }
    else if (which == 1) { w = kcw; bias = kcb; pre_off = OF_K; out_off = OF_KN; do_norm = 1; }
    else { w = vcw; bias = vcb; pre_off = OF_V; out_off = OF_VN; do_norm = 0; }

    const float* pre = (const float*)g_scratch + pre_off;
    float*       out = g_scratch + out_off;

    int row  = blockIdx.x;
    int t    = row & (TDIM - 1);
    int lane = threadIdx.x & 31;
    int h    = threadIdx.x >> 5;
    int c0   = h * 64 + lane;
    int c1   = c0 + 32;

    const float* p = pre + (size_t)row * DDIM;
    float v0 = bias[c0], v1 = bias[c1];
#pragma unroll
    for (int kk = 0; kk < 4; kk++) {
        int dt = kk - 3;
        if (t + dt >= 0) {
            const float* pr = p + (ptrdiff_t)dt * DDIM;
            v0 = fmaf(w[c0 * 4 + kk], pr[c0], v0);
            v1 = fmaf(w[c1 * 4 + kk], pr[c1], v1);
        }
    }
    v0 *= sigmoidf_(v0);   // SiLU
    v1 *= sigmoidf_(v1);

    if (do_norm) {
        float ss = v0 * v0 + v1 * v1;
#pragma unroll
        for (int o = 16; o > 0; o >>= 1) ss += __shfl_xor_sync(0xffffffffu, ss, o);
        float inv = 1.f / fmaxf(sqrtf(ss), 1e-6f);
        v0 *= inv; v1 *= inv;
    }
    out[(size_t)row * DDIM + c0] = v0;
    out[(size_t)row * DDIM + c1] = v1;
}

// ---------------------------------------------------------------------------
// Recurrence stage loader.
// ---------------------------------------------------------------------------
__device__ __forceinline__ void rec_load2(
    float* sk, float* sq, float* sv, float* sa, float* sb,
    const float* __restrict__ Kn, const float* __restrict__ Q,
    const float* __restrict__ V,
    const float* __restrict__ Al, const float* __restrict__ Be,
    size_t base, size_t abase, int c0, int t0, int tid)
{
    int e   = tid >> 4;          // 0..7
    int vec = (tid & 15) << 2;   // 0..60
    size_t go = base + (size_t)(t0 + e) * DDIM + vec;
    *(float4*)(sk + e * 64 + vec) = *(const float4*)(Kn + go);
    *(float4*)(sq + e * 64 + vec) = *(const float4*)(Q + go);
    if (tid < 32) {
        int ev = tid >> 2;
        int vv = (tid & 3) << 2;
        *(float4*)(sv + ev * 16 + vv) =
            *(const float4*)(V + base + (size_t)(t0 + ev) * DDIM + c0 + vv);
    } else if (tid < 40) {
        int ea = tid - 32;
        sa[ea] = Al[abase + (size_t)(t0 + ea) * HDIM];
    } else if (tid < 48) {
        int eb = tid - 40;
        sb[eb] = Be[abase + (size_t)(t0 + eb) * HDIM];
    }
}

// ---------------------------------------------------------------------------
// Gated delta-rule recurrence, column-split (4 CTAs per (b,h)).
// ---------------------------------------------------------------------------
__global__ __launch_bounds__(128) void rec_kernel()
{
    const float* Q  = g_scratch + OF_QN;
    const float* Kn = g_scratch + OF_KN;
    const float* V  = g_scratch + OF_VN;
    const float* Al = g_scratch + OF_A;
    const float* Be = g_scratch + OF_B;
    float*       O  = g_scratch + OF_O;

    int blk = blockIdx.x;
    int bh  = blk >> 2;
    int cq  = blk & 3;
    int c0  = cq * 16;
    int b   = bh >> 4, h = bh & 15;
    const size_t base  = (size_t)b * TDIM * DDIM + (size_t)h * 64;
    const size_t abase = (size_t)b * TDIM * HDIM + h;

    int tid = threadIdx.x;
    int g   = tid & 7;
    int jl  = tid >> 3;
    int j   = c0 + jl;
    int r0  = g * 8;

    __shared__ __align__(16) float sk[2][STAGE * 64];
    __shared__ __align__(16) float sq[2][STAGE * 64];
    __shared__ __align__(16) float sv[2][STAGE * 16];
    __shared__ float sa[2][STAGE];
    __shared__ float sb[2][STAGE];

    ull S2[4];
#pragma unroll
    for (int c = 0; c < 4; c++) S2[c] = 0ull;

    rec_load2(sk[0], sq[0], sv[0], sa[0], sb[0], Kn, Q, V, Al, Be,
              base, abase, c0, 0, tid);
    __syncthreads();

    const int nstages = TDIM / STAGE;
    for (int s = 0; s < nstages; s++) {
        const int buf = s & 1;
        if (s + 1 < nstages) {
            rec_load2(sk[buf ^ 1], sq[buf ^ 1], sv[buf ^ 1], sa[buf ^ 1], sb[buf ^ 1],
                      Kn, Q, V, Al, Be, base, abase, c0, (s + 1) * STAGE, tid);
        }
        const float* kbuf = sk[buf];
        const float* qbuf = sq[buf];
        const float* vbuf = sv[buf];

#pragma unroll
        for (int e = 0; e < STAGE; e++) {
            ull k2[4], q2[4];
            {
                const float* kp = kbuf + e * 64 + r0;
                const float* qp = qbuf + e * 64 + r0;
                *(ulonglong2*)(k2)     = *(const ulonglong2*)(kp);
                *(ulonglong2*)(k2 + 2) = *(const ulonglong2*)(kp + 4);
                *(ulonglong2*)(q2)     = *(const ulonglong2*)(qp);
                *(ulonglong2*)(q2 + 2) = *(const ulonglong2*)(qp + 4);
            }

            ull u2 = 0ull, w2 = 0ull, p2 = 0ull;
#pragma unroll
            for (int c = 0; c < 4; c++) {
                u2 = fma2_(S2[c], k2[c], u2);
                w2 = fma2_(S2[c], q2[c], w2);
                p2 = fma2_(k2[c], q2[c], p2);
            }
            float u  = hadd2_(u2);
            float w  = hadd2_(w2);
            float kq = hadd2_(p2);
#pragma unroll
            for (int off = 1; off <= 4; off <<= 1) {
                u  += __shfl_xor_sync(0xffffffffu, u,  off);
                w  += __shfl_xor_sync(0xffffffffu, w,  off);
                kq += __shfl_xor_sync(0xffffffffu, kq, off);
            }

            float a  = sa[buf][e];
            float bg = sb[buf][e];
            float vj = vbuf[e * 16 + jl];
            float bee = bg * (vj - u);
            float o = fmaf(a, w, bee * kq);

            ull a2  = pack2_(a);
            ull be2 = pack2_(bee);
#pragma unroll
            for (int c = 0; c < 4; c++)
                S2[c] = fma2_(a2, S2[c], mul2_(be2, k2[c]));

            if (g == 0)
                O[base + (size_t)(s * STAGE + e) * DDIM + j] = o;
        }
        __syncthreads();
    }
}

// ---------------------------------------------------------------------------
// RMSNorm (per head, DV=64) * rms_w * output gate g  -> Og
// ---------------------------------------------------------------------------
__global__ __launch_bounds__(512) void post_kernel(const float* __restrict__ rms_w)
{
    const float* O  = g_scratch + OF_O;
    const float* G  = g_scratch + OF_G;
    float*       Og = g_scratch + OF_OG;

    int row  = blockIdx.x;
    int lane = threadIdx.x & 31;
    int h    = threadIdx.x >> 5;
    size_t i0 = (size_t)row * DDIM + h * 64 + lane;

    float v0 = O[i0], v1 = O[i0 + 32];
    float ss = v0 * v0 + v1 * v1;
#pragma unroll
    for (int o = 16; o > 0; o >>= 1) ss += __shfl_xor_sync(0xffffffffu, ss, o);
    float inv = rsqrtf(ss * (1.f / 64.f) + 1e-6f);

    v0 = v0 * inv * rms_w[h * 64 + lane]      * G[i0];
    v1 = v1 * inv * rms_w[h * 64 + lane + 32] * G[i0 + 32];
    Og[i0]      = v0;
    Og[i0 + 32] = v1;
}

// ---------------------------------------------------------------------------
extern "C" void kernel_launch(void* const* d_in, const int* in_sizes, int n_in,
                              void* d_out, int out_size)
{
    (void)in_sizes; (void)n_in; (void)out_size;
    const float* x   = (const float*)d_in[0];
    const float* Wq  = (const float*)d_in[1];
    const float* Wk  = (const float*)d_in[2];
    const float* Wv  = (const float*)d_in[3];
    const float* Wo  = (const float*)d_in[4];
    const float* Wa  = (const float*)d_in[5];
    const float* ba  = (const float*)d_in[6];
    const float* Wb  = (const float*)d_in[7];
    const float* bb  = (const float*)d_in[8];
    const float* Wgd = (const float*)d_in[9];
    const float* Wgu = (const float*)d_in[10];
    const float* rms = (const float*)d_in[11];
    const float* qcw = (const float*)d_in[12];
    const float* qcb = (const float*)d_in[13];
    const float* kcw = (const float*)d_in[14];
    const float* kcb = (const float*)d_in[15];
    const float* vcw = (const float*)d_in[16];
    const float* vcb = (const float*)d_in[17];
    float* out = (float*)d_out;

    dim3 g1024(1024 / 128, MROWS / 128);   // (8, 64)
    dim3 g512 (512 / 128,  MROWS / 128);   // (4, 64)

    // projections (tensor cores, bf16x3)
    gemm_tc<<<g1024, 256>>>(x, 0, Wq, nullptr, OF_Q, MROWS, 1024, 1024, 0);
    gemm_tc<<<g1024, 256>>>(x, 0, Wk, nullptr, OF_K, MROWS, 1024, 1024, 0);
    gemm_tc<<<g1024, 256>>>(x, 0, Wv, nullptr, OF_V, MROWS, 1024, 1024, 0);
    // output-gate MLP: silu(x@Wgd) @ Wgu -> sigmoid
    gemm_tc<<<g512,  256>>>(x, 0, Wgd, nullptr, OF_XG, MROWS, 512, 1024, 1);
    gemm_tc<<<g1024, 256>>>(nullptr, OF_XG, Wgu, nullptr, OF_G, MROWS, 1024, 512, 2);
    // per-head scalar gates
    ab_kernel<<<MROWS / 8, 256>>>(x, Wa, ba, Wb, bb);
    // causal conv + SiLU (+ L2 norm for q,k), fused q/k/v
    {
        dim3 gc(MROWS, 3);
        conv_kernel<<<gc, 512>>>(qcw, qcb, kcw, kcb, vcw, vcb);
    }
    // sequential delta-rule recurrence (column-split, 4 CTAs per (b,h))
    rec_kernel<<<BDIM * HDIM * 4, 128>>>();
    // RMSNorm + gate
    post_kernel<<<MROWS, 512>>>(rms);
    // final projection
    gemm_tc<<<g1024, 256>>>(nullptr, OF_OG, Wo, out, 0, MROWS, 1024, 1024, 0);
}

// round 8
// speedup vs baseline: 3.0124x; 1.0327x over previous
#include <cuda_runtime.h>
#include <cuda_bf16.h>

// ---------------------------------------------------------------------------
// GatedDeltaNet (B=2,T=4096,D=1024,H=16,DK=DV=64,KS=4)
// Round 8: rec 2-step lookahead (one shfl tree per 2 steps, exact algebra).
// GEMMs: bf16x3 tensor-core (round-6 verified).
// ---------------------------------------------------------------------------

#define TDIM 4096
#define BDIM 2
#define HDIM 16
#define DDIM 1024
#define MROWS (BDIM * TDIM)
#define STAGE 8

typedef unsigned long long ull;
typedef unsigned int uint;

static constexpr size_t NM   = (size_t)MROWS * DDIM;
static constexpr size_t OF_Q  = 0;
static constexpr size_t OF_K  = 1 * NM;
static constexpr size_t OF_V  = 2 * NM;
static constexpr size_t OF_QN = 3 * NM;
static constexpr size_t OF_KN = 4 * NM;
static constexpr size_t OF_VN = 5 * NM;
static constexpr size_t OF_G  = 6 * NM;
static constexpr size_t OF_O  = 7 * NM;
static constexpr size_t OF_OG = 8 * NM;
static constexpr size_t OF_XG = 9 * NM;
static constexpr size_t OF_A  = OF_XG + (size_t)MROWS * 512;
static constexpr size_t OF_B  = OF_A + (size_t)MROWS * HDIM;
static constexpr size_t SCRATCH_FLOATS = OF_B + (size_t)MROWS * HDIM;

__device__ float g_scratch[SCRATCH_FLOATS];

__device__ __forceinline__ float sigmoidf_(float x) {
    return 1.f / (1.f + __expf(-x));
}

__device__ __forceinline__ ull fma2_(ull a, ull b, ull c) {
    ull d;
    asm("fma.rn.f32x2 %0, %1, %2, %3;" : "=l"(d) : "l"(a), "l"(b), "l"(c));
    return d;
}
__device__ __forceinline__ ull mul2_(ull a, ull b) {
    ull d;
    asm("mul.rn.f32x2 %0, %1, %2;" : "=l"(d) : "l"(a), "l"(b));
    return d;
}
__device__ __forceinline__ ull pack2_(float x) {
    ull r;
    asm("mov.b64 %0, {%1, %1};" : "=l"(r) : "r"(__float_as_uint(x)));
    return r;
}
__device__ __forceinline__ float hadd2_(ull a) {
    unsigned lo, hi;
    asm("mov.b64 {%0, %1}, %2;" : "=r"(lo), "=r"(hi) : "l"(a));
    return __uint_as_float(lo) + __uint_as_float(hi);
}

__device__ __forceinline__ void mma_bf16(float c[4],
    uint a0, uint a1, uint a2, uint a3, uint b0, uint b1)
{
    asm volatile(
        "mma.sync.aligned.m16n8k16.row.col.f32.bf16.bf16.f32 "
        "{%0,%1,%2,%3},{%4,%5,%6,%7},{%8,%9},{%0,%1,%2,%3};"
        : "+f"(c[0]), "+f"(c[1]), "+f"(c[2]), "+f"(c[3])
        : "r"(a0), "r"(a1), "r"(a2), "r"(a3), "r"(b0), "r"(b1));
}
__device__ __forceinline__ void ldsm_x4(uint& r0, uint& r1, uint& r2, uint& r3,
                                        const void* p)
{
    uint a = (uint)__cvta_generic_to_shared(p);
    asm volatile("ldmatrix.sync.aligned.m8n8.x4.shared.b16 {%0,%1,%2,%3},[%4];"
                 : "=r"(r0), "=r"(r1), "=r"(r2), "=r"(r3) : "r"(a));
}
__device__ __forceinline__ void ldsm_x2t(uint& r0, uint& r1, const void* p)
{
    uint a = (uint)__cvta_generic_to_shared(p);
    asm volatile("ldmatrix.sync.aligned.m8n8.x2.trans.shared.b16 {%0,%1},[%2];"
                 : "=r"(r0), "=r"(r1) : "r"(a));
}
__device__ __forceinline__ void split4(float4 v, uint& h01, uint& h23,
                                       uint& l01, uint& l23)
{
    __nv_bfloat162 h01b = __floats2bfloat162_rn(v.x, v.y);
    __nv_bfloat162 h23b = __floats2bfloat162_rn(v.z, v.w);
    float r0 = v.x - __bfloat162float(h01b.x);
    float r1 = v.y - __bfloat162float(h01b.y);
    float r2 = v.z - __bfloat162float(h23b.x);
    float r3 = v.w - __bfloat162float(h23b.y);
    __nv_bfloat162 l01b = __floats2bfloat162_rn(r0, r1);
    __nv_bfloat162 l23b = __floats2bfloat162_rn(r2, r3);
    h01 = *(uint*)&h01b;  h23 = *(uint*)&h23b;
    l01 = *(uint*)&l01b;  l23 = *(uint*)&l23b;
}

#define A_STRIDE 12
#define B_STRIDE 68

__global__ __launch_bounds__(256) void gemm_tc(
    const float* __restrict__ Aext, size_t Aoff,
    const float* __restrict__ W,
    float* __restrict__ Cext, size_t Coff,
    int M, int N, int K, int act)
{
    const float* A = Aext ? Aext : (const float*)g_scratch + Aoff;
    float*       C = Cext ? Cext : g_scratch + Coff;

    __shared__ __align__(16) uint As[2][2][128][A_STRIDE];
    __shared__ __align__(16) uint Bs[2][2][16][B_STRIDE];

    const int tid  = threadIdx.x;
    const int brow = blockIdx.y * 128;
    const int bcol = blockIdx.x * 128;

    const int lane = tid & 31;
    const int warp = tid >> 5;
    const int wm   = warp >> 2;
    const int wn   = warp & 3;
    const int gid  = lane >> 2;
    const int tig  = lane & 3;

    const int am0 = tid >> 2;
    const int ak0 = (tid & 3) << 2;
    const int bk0 = tid >> 5;
    const int bn0 = (tid & 31) << 2;

    const float* ApA = A + (size_t)(brow + am0) * K + ak0;
    const float* ApB = ApA + (size_t)64 * K;
    const float* BpA = W + (size_t)bk0 * N + bcol + bn0;
    const float* BpB = BpA + (size_t)8 * N;

    float acc[4][4][4];
#pragma unroll
    for (int i = 0; i < 4; i++)
#pragma unroll
        for (int j = 0; j < 4; j++)
#pragma unroll
            for (int c = 0; c < 4; c++) acc[i][j][c] = 0.f;

    const int a_lrow = lane & 15;
    const int a_koff = (lane >> 4) * 4;
    const int b_lrow = lane & 15;

    float4 avA, avB, bvA, bvB;
    avA = *(const float4*)(ApA);
    avB = *(const float4*)(ApB);
    bvA = *(const float4*)(BpA);
    bvB = *(const float4*)(BpB);
    {
        uint h01, h23, l01, l23;
        split4(avA, h01, h23, l01, l23);
        *(uint2*)&As[0][0][am0][ak0 >> 1]      = make_uint2(h01, h23);
        *(uint2*)&As[0][1][am0][ak0 >> 1]      = make_uint2(l01, l23);
        split4(avB, h01, h23, l01, l23);
        *(uint2*)&As[0][0][am0 + 64][ak0 >> 1] = make_uint2(h01, h23);
        *(uint2*)&As[0][1][am0 + 64][ak0 >> 1] = make_uint2(l01, l23);
        split4(bvA, h01, h23, l01, l23);
        *(uint2*)&Bs[0][0][bk0][bn0 >> 1]      = make_uint2(h01, h23);
        *(uint2*)&Bs[0][1][bk0][bn0 >> 1]      = make_uint2(l01, l23);
        split4(bvB, h01, h23, l01, l23);
        *(uint2*)&Bs[0][0][bk0 + 8][bn0 >> 1]  = make_uint2(h01, h23);
        *(uint2*)&Bs[0][1][bk0 + 8][bn0 >> 1]  = make_uint2(l01, l23);
    }
    __syncthreads();

    const int nk = K >> 4;
    for (int kt = 0; kt < nk; kt++) {
        const int buf = kt & 1;
        if (kt + 1 < nk) {
            const int ko = (kt + 1) << 4;
            avA = *(const float4*)(ApA + ko);
            avB = *(const float4*)(ApB + ko);
            bvA = *(const float4*)(BpA + (size_t)ko * N);
            bvB = *(const float4*)(BpB + (size_t)ko * N);
        }

        uint Ah[4][4], Al[4][4], Bh[4][2], Bl[4][2];
#pragma unroll
        for (int mt = 0; mt < 4; mt++) {
            int row = wm * 64 + mt * 16 + a_lrow;
            ldsm_x4(Ah[mt][0], Ah[mt][1], Ah[mt][2], Ah[mt][3],
                    &As[buf][0][row][a_koff]);
            ldsm_x4(Al[mt][0], Al[mt][1], Al[mt][2], Al[mt][3],
                    &As[buf][1][row][a_koff]);
        }
#pragma unroll
        for (int nt = 0; nt < 4; nt++) {
            int nu = wn * 16 + nt * 4;
            ldsm_x2t(Bh[nt][0], Bh[nt][1], &Bs[buf][0][b_lrow][nu]);
            ldsm_x2t(Bl[nt][0], Bl[nt][1], &Bs[buf][1][b_lrow][nu]);
        }

#pragma unroll
        for (int mt = 0; mt < 4; mt++) {
#pragma unroll
            for (int nt = 0; nt < 4; nt++) {
                mma_bf16(acc[mt][nt], Ah[mt][0], Ah[mt][1], Ah[mt][2], Ah[mt][3],
                         Bh[nt][0], Bh[nt][1]);
                mma_bf16(acc[mt][nt], Ah[mt][0], Ah[mt][1], Ah[mt][2], Ah[mt][3],
                         Bl[nt][0], Bl[nt][1]);
                mma_bf16(acc[mt][nt], Al[mt][0], Al[mt][1], Al[mt][2], Al[mt][3],
                         Bh[nt][0], Bh[nt][1]);
            }
        }

        if (kt + 1 < nk) {
            const int nb = buf ^ 1;
            uint h01, h23, l01, l23;
            split4(avA, h01, h23, l01, l23);
            *(uint2*)&As[nb][0][am0][ak0 >> 1]      = make_uint2(h01, h23);
            *(uint2*)&As[nb][1][am0][ak0 >> 1]      = make_uint2(l01, l23);
            split4(avB, h01, h23, l01, l23);
            *(uint2*)&As[nb][0][am0 + 64][ak0 >> 1] = make_uint2(h01, h23);
            *(uint2*)&As[nb][1][am0 + 64][ak0 >> 1] = make_uint2(l01, l23);
            split4(bvA, h01, h23, l01, l23);
            *(uint2*)&Bs[nb][0][bk0][bn0 >> 1]      = make_uint2(h01, h23);
            *(uint2*)&Bs[nb][1][bk0][bn0 >> 1]      = make_uint2(l01, l23);
            split4(bvB, h01, h23, l01, l23);
            *(uint2*)&Bs[nb][0][bk0 + 8][bn0 >> 1]  = make_uint2(h01, h23);
            *(uint2*)&Bs[nb][1][bk0 + 8][bn0 >> 1]  = make_uint2(l01, l23);
            __syncthreads();
        }
    }

#pragma unroll
    for (int mt = 0; mt < 4; mt++) {
        int row0 = brow + wm * 64 + mt * 16 + gid;
#pragma unroll
        for (int nt = 0; nt < 4; nt++) {
            int col0 = bcol + wn * 32 + nt * 8 + 2 * tig;
            float c0 = acc[mt][nt][0], c1 = acc[mt][nt][1];
            float c2 = acc[mt][nt][2], c3 = acc[mt][nt][3];
            if (act == 1) {
                c0 *= sigmoidf_(c0); c1 *= sigmoidf_(c1);
                c2 *= sigmoidf_(c2); c3 *= sigmoidf_(c3);
            } else if (act == 2) {
                c0 = sigmoidf_(c0); c1 = sigmoidf_(c1);
                c2 = sigmoidf_(c2); c3 = sigmoidf_(c3);
            }
            *(float2*)(C + (size_t)row0 * N + col0)       = make_float2(c0, c1);
            *(float2*)(C + (size_t)(row0 + 8) * N + col0) = make_float2(c2, c3);
        }
    }
}

__global__ __launch_bounds__(256) void ab_kernel(
    const float* __restrict__ x,
    const float* __restrict__ Wa, const float* __restrict__ ba,
    const float* __restrict__ Wb, const float* __restrict__ bb)
{
    int row  = blockIdx.x * 8 + (threadIdx.x >> 5);
    int lane = threadIdx.x & 31;
    const float* xr = x + (size_t)row * DDIM;
    const float* W  = (lane < 16) ? Wa : Wb;
    int h = lane & 15;

    float s0 = 0.f, s1 = 0.f, s2 = 0.f, s3 = 0.f;
#pragma unroll 4
    for (int i = 0; i < DDIM; i += 4) {
        s0 = fmaf(xr[i + 0], W[(i + 0) * HDIM + h], s0);
        s1 = fmaf(xr[i + 1], W[(i + 1) * HDIM + h], s1);
        s2 = fmaf(xr[i + 2], W[(i + 2) * HDIM + h], s2);
        s3 = fmaf(xr[i + 3], W[(i + 3) * HDIM + h], s3);
    }
    float s = (s0 + s1) + (s2 + s3);
    if (lane < 16) {
        float sg = sigmoidf_(s + ba[h]);
        g_scratch[OF_A + (size_t)row * HDIM + h] = fminf(fmaxf(sg, 0.1f), 1.0f);
    } else {
        float sg = sigmoidf_(s + bb[h]);
        g_scratch[OF_B + (size_t)row * HDIM + h] = fminf(sg, 1.0f);
    }
}

__global__ __launch_bounds__(512) void conv_kernel(
    const float* __restrict__ qcw, const float* __restrict__ qcb,
    const float* __restrict__ kcw, const float* __restrict__ kcb,
    const float* __restrict__ vcw, const float* __restrict__ vcb)
{
    int which = blockIdx.y;
    const float* w;
    const float* bias;
    size_t pre_off, out_off;
    int do_norm;
    if (which == 0) { w = qcw; bias = qcb; pre_off = OF_Q; out_off = OF_QN; do_norm = 1; }
    else if (which == 1) { w = kcw; bias = kcb; pre_off = OF_K; out_off = OF_KN; do_norm = 1; }
    else { w = vcw; bias = vcb; pre_off = OF_V; out_off = OF_VN; do_norm = 0; }

    const float* pre = (const float*)g_scratch + pre_off;
    float*       out = g_scratch + out_off;

    int row  = blockIdx.x;
    int t    = row & (TDIM - 1);
    int lane = threadIdx.x & 31;
    int h    = threadIdx.x >> 5;
    int c0   = h * 64 + lane;
    int c1   = c0 + 32;

    const float* p = pre + (size_t)row * DDIM;
    float v0 = bias[c0], v1 = bias[c1];
#pragma unroll
    for (int kk = 0; kk < 4; kk++) {
        int dt = kk - 3;
        if (t + dt >= 0) {
            const float* pr = p + (ptrdiff_t)dt * DDIM;
            v0 = fmaf(w[c0 * 4 + kk], pr[c0], v0);
            v1 = fmaf(w[c1 * 4 + kk], pr[c1], v1);
        }
    }
    v0 *= sigmoidf_(v0);
    v1 *= sigmoidf_(v1);

    if (do_norm) {
        float ss = v0 * v0 + v1 * v1;
#pragma unroll
        for (int o = 16; o > 0; o >>= 1) ss += __shfl_xor_sync(0xffffffffu, ss, o);
        float inv = 1.f / fmaxf(sqrtf(ss), 1e-6f);
        v0 *= inv; v1 *= inv;
    }
    out[(size_t)row * DDIM + c0] = v0;
    out[(size_t)row * DDIM + c1] = v1;
}

__device__ __forceinline__ void rec_load2(
    float* sk, float* sq, float* sv, float* sa, float* sb,
    const float* __restrict__ Kn, const float* __restrict__ Q,
    const float* __restrict__ V,
    const float* __restrict__ Al, const float* __restrict__ Be,
    size_t base, size_t abase, int c0, int t0, int tid)
{
    int e   = tid >> 4;
    int vec = (tid & 15) << 2;
    size_t go = base + (size_t)(t0 + e) * DDIM + vec;
    *(float4*)(sk + e * 64 + vec) = *(const float4*)(Kn + go);
    *(float4*)(sq + e * 64 + vec) = *(const float4*)(Q + go);
    if (tid < 32) {
        int ev = tid >> 2;
        int vv = (tid & 3) << 2;
        *(float4*)(sv + ev * 16 + vv) =
            *(const float4*)(V + base + (size_t)(t0 + ev) * DDIM + c0 + vv);
    } else if (tid < 40) {
        int ea = tid - 32;
        sa[ea] = Al[abase + (size_t)(t0 + ea) * HDIM];
    } else if (tid < 48) {
        int eb = tid - 40;
        sb[eb] = Be[abase + (size_t)(t0 + eb) * HDIM];
    }
}

// 2-step lookahead delta-rule recurrence (exact reordering).
__global__ __launch_bounds__(128) void rec_kernel()
{
    const float* Q  = g_scratch + OF_QN;
    const float* Kn = g_scratch + OF_KN;
    const float* V  = g_scratch + OF_VN;
    const float* Al = g_scratch + OF_A;
    const float* Be = g_scratch + OF_B;
    float*       O  = g_scratch + OF_O;

    int blk = blockIdx.x;
    int bh  = blk >> 2;
    int cq  = blk & 3;
    int c0  = cq * 16;
    int b   = bh >> 4, h = bh & 15;
    const size_t base  = (size_t)b * TDIM * DDIM + (size_t)h * 64;
    const size_t abase = (size_t)b * TDIM * HDIM + h;

    int tid = threadIdx.x;
    int g   = tid & 7;
    int jl  = tid >> 3;
    int j   = c0 + jl;
    int r0  = g * 8;

    __shared__ __align__(16) float sk[2][STAGE * 64];
    __shared__ __align__(16) float sq[2][STAGE * 64];
    __shared__ __align__(16) float sv[2][STAGE * 16];
    __shared__ float sa[2][STAGE];
    __shared__ float sb[2][STAGE];

    ull S2[4];
#pragma unroll
    for (int c = 0; c < 4; c++) S2[c] = 0ull;

    rec_load2(sk[0], sq[0], sv[0], sa[0], sb[0], Kn, Q, V, Al, Be,
              base, abase, c0, 0, tid);
    __syncthreads();

    const int nstages = TDIM / STAGE;
    for (int s = 0; s < nstages; s++) {
        const int buf = s & 1;
        if (s + 1 < nstages) {
            rec_load2(sk[buf ^ 1], sq[buf ^ 1], sv[buf ^ 1], sa[buf ^ 1], sb[buf ^ 1],
                      Kn, Q, V, Al, Be, base, abase, c0, (s + 1) * STAGE, tid);
        }
        const float* kbuf = sk[buf];
        const float* qbuf = sq[buf];
        const float* vbuf = sv[buf];

#pragma unroll
        for (int e = 0; e < STAGE; e += 2) {
            ull k0[4], k1[4], q0[4], q1[4];
            {
                const float* kp0 = kbuf + e * 64 + r0;
                const float* kp1 = kbuf + (e + 1) * 64 + r0;
                const float* qp0 = qbuf + e * 64 + r0;
                const float* qp1 = qbuf + (e + 1) * 64 + r0;
                *(ulonglong2*)(k0)     = *(const ulonglong2*)(kp0);
                *(ulonglong2*)(k0 + 2) = *(const ulonglong2*)(kp0 + 4);
                *(ulonglong2*)(k1)     = *(const ulonglong2*)(kp1);
                *(ulonglong2*)(k1 + 2) = *(const ulonglong2*)(kp1 + 4);
                *(ulonglong2*)(q0)     = *(const ulonglong2*)(qp0);
                *(ulonglong2*)(q0 + 2) = *(const ulonglong2*)(qp0 + 4);
                *(ulonglong2*)(q1)     = *(const ulonglong2*)(qp1);
                *(ulonglong2*)(q1 + 2) = *(const ulonglong2*)(qp1 + 4);
            }

            ull au0 = 0, ax1 = 0, aw0 = 0, ay1 = 0;
            ull akk = 0, ap00 = 0, ap01 = 0, ap11 = 0;
#pragma unroll
            for (int c = 0; c < 4; c++) {
                au0  = fma2_(S2[c], k0[c], au0);
                ax1  = fma2_(S2[c], k1[c], ax1);
                aw0  = fma2_(S2[c], q0[c], aw0);
                ay1  = fma2_(S2[c], q1[c], ay1);
                akk  = fma2_(k0[c], k1[c], akk);
                ap00 = fma2_(k0[c], q0[c], ap00);
                ap01 = fma2_(k0[c], q1[c], ap01);
                ap11 = fma2_(k1[c], q1[c], ap11);
            }
            float u0  = hadd2_(au0),  x1  = hadd2_(ax1);
            float w0  = hadd2_(aw0),  y1  = hadd2_(ay1);
            float kk  = hadd2_(akk),  p00 = hadd2_(ap00);
            float p01 = hadd2_(ap01), p11 = hadd2_(ap11);

#pragma unroll
            for (int off = 1; off <= 4; off <<= 1) {
                u0  += __shfl_xor_sync(0xffffffffu, u0,  off);
                x1  += __shfl_xor_sync(0xffffffffu, x1,  off);
                w0  += __shfl_xor_sync(0xffffffffu, w0,  off);
                y1  += __shfl_xor_sync(0xffffffffu, y1,  off);
                kk  += __shfl_xor_sync(0xffffffffu, kk,  off);
                p00 += __shfl_xor_sync(0xffffffffu, p00, off);
                p01 += __shfl_xor_sync(0xffffffffu, p01, off);
                p11 += __shfl_xor_sync(0xffffffffu, p11, off);
            }

            float a0 = sa[buf][e],     b0 = sb[buf][e];
            float a1 = sa[buf][e + 1], b1 = sb[buf][e + 1];
            float v0 = vbuf[e * 16 + jl];
            float v1 = vbuf[(e + 1) * 16 + jl];

            float bee0 = b0 * (v0 - u0);
            float o0   = fmaf(a0, w0, bee0 * p00);
            float u1   = fmaf(a0, x1, bee0 * kk);
            float bee1 = b1 * (v1 - u1);
            float w1   = fmaf(a0, y1, bee0 * p01);
            float o1   = fmaf(a1, w1, bee1 * p11);

            ull c01 = pack2_(a0 * a1);
            ull c0k = pack2_(a1 * bee0);
            ull c1k = pack2_(bee1);
#pragma unroll
            for (int c = 0; c < 4; c++)
                S2[c] = fma2_(c01, S2[c], fma2_(c0k, k0[c], mul2_(c1k, k1[c])));

            if (g == 0) {
                size_t oo = base + (size_t)(s * STAGE + e) * DDIM + j;
                O[oo]        = o0;
                O[oo + DDIM] = o1;
            }
        }
        __syncthreads();
    }
}

__global__ __launch_bounds__(512) void post_kernel(const float* __restrict__ rms_w)
{
    const float* O  = g_scratch + OF_O;
    const float* G  = g_scratch + OF_G;
    float*       Og = g_scratch + OF_OG;

    int row  = blockIdx.x;
    int lane = threadIdx.x & 31;
    int h    = threadIdx.x >> 5;
    size_t i0 = (size_t)row * DDIM + h * 64 + lane;

    float v0 = O[i0], v1 = O[i0 + 32];
    float ss = v0 * v0 + v1 * v1;
#pragma unroll
    for (int o = 16; o > 0; o >>= 1) ss += __shfl_xor_sync(0xffffffffu, ss, o);
    float inv = rsqrtf(ss * (1.f / 64.f) + 1e-6f);

    v0 = v0 * inv * rms_w[h * 64 + lane]      * G[i0];
    v1 = v1 * inv * rms_w[h * 64 + lane + 32] * G[i0 + 32];
    Og[i0]      = v0;
    Og[i0 + 32] = v1;
}

extern "C" void kernel_launch(void* const* d_in, const int* in_sizes, int n_in,
                              void* d_out, int out_size)
{
    (void)in_sizes; (void)n_in; (void)out_size;
    const float* x   = (const float*)d_in[0];
    const float* Wq  = (const float*)d_in[1];
    const float* Wk  = (const float*)d_in[2];
    const float* Wv  = (const float*)d_in[3];
    const float* Wo  = (const float*)d_in[4];
    const float* Wa  = (const float*)d_in[5];
    const float* ba  = (const float*)d_in[6];
    const float* Wb  = (const float*)d_in[7];
    const float* bb  = (const float*)d_in[8];
    const float* Wgd = (const float*)d_in[9];
    const float* Wgu = (const float*)d_in[10];
    const float* rms = (const float*)d_in[11];
    const float* qcw = (const float*)d_in[12];
    const float* qcb = (const float*)d_in[13];
    const float* kcw = (const float*)d_in[14];
    const float* kcb = (const float*)d_in[15];
    const float* vcw = (const float*)d_in[16];
    const float* vcb = (const float*)d_in[17];
    float* out = (float*)d_out;

    dim3 g1024(1024 / 128, MROWS / 128);
    dim3 g512 (512 / 128,  MROWS / 128);

    gemm_tc<<<g1024, 256>>>(x, 0, Wq, nullptr, OF_Q, MROWS, 1024, 1024, 0);
    gemm_tc<<<g1024, 256>>>(x, 0, Wk, nullptr, OF_K, MROWS, 1024, 1024, 0);
    gemm_tc<<<g1024, 256>>>(x, 0, Wv, nullptr, OF_V, MROWS, 1024, 1024, 0);
    gemm_tc<<<g512,  256>>>(x, 0, Wgd, nullptr, OF_XG, MROWS, 512, 1024, 1);
    gemm_tc<<<g1024, 256>>>(nullptr, OF_XG, Wgu, nullptr, OF_G, MROWS, 1024, 512, 2);
    ab_kernel<<<MROWS / 8, 256>>>(x, Wa, ba, Wb, bb);
    {
        dim3 gc(MROWS, 3);
        conv_kernel<<<gc, 512>>>(qcw, qcb, kcw, kcb, vcw, vcb);
    }
    rec_kernel<<<BDIM * HDIM * 4, 128>>>();
    post_kernel<<<MROWS, 512>>>(rms);
    gemm_tc<<<g1024, 256>>>(nullptr, OF_OG, Wo, out, 0, MROWS, 1024, 1024, 0);
}